// round 2
// baseline (speedup 1.0000x reference)
#include <cuda_runtime.h>
#include <math.h>

#define B_SZ 32
#define D    64
#define HWD  64
#define NQ   4096
#define MKV  256
#define HEADS 2
#define DKH  32
#define DVH  32
#define DN   (D*NQ)   // 262144 per batch

// ---------------- scratch (no allocation allowed) ----------------
__device__ float g_stats[2 * B_SZ];                    // mu, rstd per batch
__device__ float g_K[B_SZ * HEADS * DKH * MKV];        // [b][h][d][j]
__device__ float g_V[B_SZ * HEADS * MKV * DVH];        // [b][h][j][d]

// ---------------- kernel 1: layernorm stats ----------------
__global__ void ln_stats_kernel(const float* __restrict__ x) {
    int b = blockIdx.x;
    const float4* xb = (const float4*)(x + (size_t)b * DN);
    float s1 = 0.f, s2 = 0.f;
    for (int i = threadIdx.x; i < DN / 4; i += blockDim.x) {
        float4 v = xb[i];
        s1 += v.x + v.y + v.z + v.w;
        s2 += v.x*v.x + v.y*v.y + v.z*v.z + v.w*v.w;
    }
    #pragma unroll
    for (int o = 16; o > 0; o >>= 1) {
        s1 += __shfl_xor_sync(~0u, s1, o);
        s2 += __shfl_xor_sync(~0u, s2, o);
    }
    __shared__ float r1[32], r2[32];
    int wid = threadIdx.x >> 5, lid = threadIdx.x & 31;
    if (lid == 0) { r1[wid] = s1; r2[wid] = s2; }
    __syncthreads();
    if (threadIdx.x == 0) {
        float t1 = 0.f, t2 = 0.f;
        int nw = blockDim.x >> 5;
        for (int i = 0; i < nw; i++) { t1 += r1[i]; t2 += r2[i]; }
        float inv = 1.f / (float)DN;
        float mu  = t1 * inv;
        float var = t2 * inv - mu * mu;
        g_stats[2*b]   = mu;
        g_stats[2*b+1] = rsqrtf(var + 1e-5f);
    }
}

// ---------------- kernel 2: dw-conv + K/V projections ----------------
// smem: kv[256][68], Wks[64][68], Wvs[64][68], Wdws[64][16], xs[4][4096]
__global__ void __launch_bounds__(256) kv_kernel(
    const float* __restrict__ x, const float* __restrict__ W_dw,
    const float* __restrict__ b_dw,
    const float* __restrict__ Wk, const float* __restrict__ bk,
    const float* __restrict__ Wv, const float* __restrict__ bv)
{
    int b = blockIdx.x;
    int t = threadIdx.x;
    extern __shared__ float sm[];
    float* kv   = sm;                  // 256*68 = 17408
    float* Wks  = kv + 256*68;         // 4352
    float* Wvs  = Wks + 64*68;         // 4352
    float* Wdws = Wvs + 64*68;         // 1024
    float* xs   = Wdws + 1024;         // 16384

    for (int i = t; i < 64*64; i += 256) {
        int e = i >> 6, c = i & 63;
        Wks[e*68 + c] = Wk[i];
        Wvs[e*68 + c] = Wv[i];
    }
    for (int i = t; i < 1024; i += 256) Wdws[i] = W_dw[i];

    int ky = t >> 4, kx = t & 15;   // m = t = ky*16 + kx
    const float* xb = x + (size_t)b * DN;

    for (int cc = 0; cc < 64; cc += 4) {
        __syncthreads();
        for (int i = t*4; i < 4*4096; i += 256*4)
            *(float4*)&xs[i] = *(const float4*)&xb[cc*4096 + i];
        __syncthreads();
        #pragma unroll
        for (int cl = 0; cl < 4; cl++) {
            float acc = b_dw[cc + cl];
            const float* xr = &xs[cl*4096 + ky*256 + kx*4];
            const float* wr = &Wdws[(cc + cl)*16];
            #pragma unroll
            for (int sy = 0; sy < 4; sy++)
                #pragma unroll
                for (int sx = 0; sx < 4; sx++)
                    acc += xr[sy*64 + sx] * wr[sy*4 + sx];
            kv[t*68 + cc + cl] = acc;
        }
    }
    __syncthreads();

    int mg = t & 31;
    int e0 = (t >> 5) * 8;
    float acc[8][8];

    // ---- K projection ----
    #pragma unroll
    for (int ee = 0; ee < 8; ee++) {
        float bias = bk[e0 + ee];
        #pragma unroll
        for (int mm = 0; mm < 8; mm++) acc[mm][ee] = bias;
    }
    for (int c = 0; c < 64; c += 4) {
        float4 kvv[8], wv[8];
        #pragma unroll
        for (int mm = 0; mm < 8; mm++) kvv[mm] = *(float4*)&kv[(mg + 32*mm)*68 + c];
        #pragma unroll
        for (int ee = 0; ee < 8; ee++) wv[ee] = *(float4*)&Wks[(e0 + ee)*68 + c];
        #pragma unroll
        for (int mm = 0; mm < 8; mm++)
            #pragma unroll
            for (int ee = 0; ee < 8; ee++)
                acc[mm][ee] += kvv[mm].x*wv[ee].x + kvv[mm].y*wv[ee].y
                             + kvv[mm].z*wv[ee].z + kvv[mm].w*wv[ee].w;
    }
    #pragma unroll
    for (int ee = 0; ee < 8; ee++) {
        int e = e0 + ee, h = e >> 5, d = e & 31;
        float* dst = &g_K[(((size_t)b*HEADS + h)*DKH + d)*MKV];
        #pragma unroll
        for (int mm = 0; mm < 8; mm++) dst[mg + 32*mm] = acc[mm][ee];
    }

    // ---- V projection ----
    #pragma unroll
    for (int ee = 0; ee < 8; ee++) {
        float bias = bv[e0 + ee];
        #pragma unroll
        for (int mm = 0; mm < 8; mm++) acc[mm][ee] = bias;
    }
    for (int c = 0; c < 64; c += 4) {
        float4 kvv[8], wv[8];
        #pragma unroll
        for (int mm = 0; mm < 8; mm++) kvv[mm] = *(float4*)&kv[(mg + 32*mm)*68 + c];
        #pragma unroll
        for (int ee = 0; ee < 8; ee++) wv[ee] = *(float4*)&Wvs[(e0 + ee)*68 + c];
        #pragma unroll
        for (int mm = 0; mm < 8; mm++)
            #pragma unroll
            for (int ee = 0; ee < 8; ee++)
                acc[mm][ee] += kvv[mm].x*wv[ee].x + kvv[mm].y*wv[ee].y
                             + kvv[mm].z*wv[ee].z + kvv[mm].w*wv[ee].w;
    }
    #pragma unroll
    for (int ee = 0; ee < 8; ee++) {
        int e = e0 + ee, h = e >> 5, d = e & 31;
        #pragma unroll
        for (int mm = 0; mm < 8; mm++)
            g_V[(((size_t)b*HEADS + h)*MKV + (mg + 32*mm))*DVH + d] = acc[mm][ee];
    }
}

// ---------------- kernel 3: fused LN + Qproj + attention + out proj ----------------
// smem layout (floats):
//   q_s   @ 0      [64][65]   = 4160
//   p_s   @ 4160   [64][256]  = 16384   (phase1 alias: xn_s [64][65])
//   kt_s  @ 20544  [32][256]  = 8192    (phase1 alias: Wq_s [64][68]; phase3: Wot [64][68])
//   v_s   @ 28736  [256][36]  = 9216
//   tmp_s @ 37952  [64][68]   = 4352
//   total 42304 floats = 169216 B
__global__ void __launch_bounds__(256) attn_kernel(
    const float* __restrict__ x,
    const float* __restrict__ Wq, const float* __restrict__ bq,
    const float* __restrict__ Wo, const float* __restrict__ bo,
    const float* __restrict__ Bbias,
    float* __restrict__ out)
{
    int b  = blockIdx.y;
    int n0 = blockIdx.x * 64;
    int t  = threadIdx.x;
    int lane = t & 31, w = t >> 5;

    extern __shared__ float sm[];
    float* q_s   = sm;
    float* p_s   = sm + 4160;
    float* xn_s  = p_s;
    float* kt_s  = sm + 20544;
    float* v_s   = sm + 28736;
    float* tmp_s = sm + 37952;

    float mu = g_stats[2*b], rstd = g_stats[2*b+1];
    const float* xb = x + (size_t)b * DN;

    // Wq into kt region ([e][c] pitch 68)
    float* wq_s = kt_s;
    for (int i = t; i < 4096; i += 256) {
        int e = i >> 6, c = i & 63;
        wq_s[e*68 + c] = Wq[i];
    }
    // normalized x tile: xn_s[query][c], pitch 65 (conflict-free transpose writes)
    for (int i = t; i < 4096; i += 256) {
        int c = i >> 6, col = i & 63;
        float v = xb[c*4096 + n0 + col];
        xn_s[col*65 + c] = (v - mu) * rstd;
    }
    __syncthreads();

    // Q projection: thread -> (query i = t&63, 16 outputs e0..e0+15)
    {
        int qi = t & 63;
        int e0 = (t >> 6) * 16;
        float acc[16];
        #pragma unroll
        for (int ee = 0; ee < 16; ee++) acc[ee] = bq[e0 + ee];
        for (int c = 0; c < 64; c += 4) {
            float xv0 = xn_s[qi*65 + c + 0];
            float xv1 = xn_s[qi*65 + c + 1];
            float xv2 = xn_s[qi*65 + c + 2];
            float xv3 = xn_s[qi*65 + c + 3];
            #pragma unroll
            for (int ee = 0; ee < 16; ee++) {
                float4 wv = *(float4*)&wq_s[(e0 + ee)*68 + c];
                acc[ee] += xv0*wv.x + xv1*wv.y + xv2*wv.z + xv3*wv.w;
            }
        }
        #pragma unroll
        for (int ee = 0; ee < 16; ee++) q_s[qi*65 + e0 + ee] = acc[ee];
    }
    __syncthreads();

    const float scale = 0.17677669529663687f;   // 32^-0.5
    const float LOG2E = 1.4426950408889634f;

    for (int h = 0; h < HEADS; h++) {
        // stage K^T [d][j] and V [j][d]
        const float* Kg = &g_K[((size_t)b*HEADS + h)*DKH*MKV];
        const float* Vg = &g_V[((size_t)b*HEADS + h)*MKV*DVH];
        for (int i = t; i < DKH*MKV; i += 256) kt_s[i] = Kg[i];
        for (int i = t; i < MKV*DVH; i += 256) {
            int j = i >> 5, d = i & 31;
            v_s[j*36 + d] = Vg[i];
        }
        __syncthreads();

        // QK: warp w owns queries [8w, 8w+8); lane owns j = lane + 32*jj
        float s[8][8];
        #pragma unroll
        for (int ii = 0; ii < 8; ii++)
            #pragma unroll
            for (int jj = 0; jj < 8; jj++) s[ii][jj] = 0.f;

        for (int d = 0; d < 32; d++) {
            float kr[8], qr[8];
            #pragma unroll
            for (int jj = 0; jj < 8; jj++) kr[jj] = kt_s[d*256 + lane + 32*jj];
            #pragma unroll
            for (int ii = 0; ii < 8; ii++) qr[ii] = q_s[(8*w + ii)*65 + h*32 + d];
            #pragma unroll
            for (int ii = 0; ii < 8; ii++)
                #pragma unroll
                for (int jj = 0; jj < 8; jj++) s[ii][jj] += qr[ii] * kr[jj];
        }

        // bias + softmax (register rows, warp butterfly)
        const float* Bp = Bbias + ((size_t)(h*NQ + n0 + 8*w))*MKV + lane;
        #pragma unroll
        for (int ii = 0; ii < 8; ii++) {
            #pragma unroll
            for (int jj = 0; jj < 8; jj++)
                s[ii][jj] = fmaf(s[ii][jj], scale, Bp[ii*MKV + 32*jj]);
            float mx = s[ii][0];
            #pragma unroll
            for (int jj = 1; jj < 8; jj++) mx = fmaxf(mx, s[ii][jj]);
            #pragma unroll
            for (int o = 16; o > 0; o >>= 1) mx = fmaxf(mx, __shfl_xor_sync(~0u, mx, o));
            float sum = 0.f;
            #pragma unroll
            for (int jj = 0; jj < 8; jj++) {
                s[ii][jj] = exp2f((s[ii][jj] - mx) * LOG2E);
                sum += s[ii][jj];
            }
            #pragma unroll
            for (int o = 16; o > 0; o >>= 1) sum += __shfl_xor_sync(~0u, sum, o);
            float inv = __fdividef(1.f, sum);
            #pragma unroll
            for (int jj = 0; jj < 8; jj++)
                p_s[(8*w + ii)*256 + lane + 32*jj] = s[ii][jj] * inv;
        }
        __syncthreads();

        // AV: thread -> (2 queries i0,i0+1) x (4 dims d0..d0+3)
        {
            int d0 = (t & 7) * 4;
            int i0 = (t >> 3) * 2;
            float4 a0 = {0,0,0,0}, a1 = {0,0,0,0};
            #pragma unroll 4
            for (int j = 0; j < 256; j++) {
                float p0 = p_s[i0*256 + j];
                float p1 = p_s[(i0+1)*256 + j];
                float4 vv = *(float4*)&v_s[j*36 + d0];
                a0.x += p0*vv.x; a0.y += p0*vv.y; a0.z += p0*vv.z; a0.w += p0*vv.w;
                a1.x += p1*vv.x; a1.y += p1*vv.y; a1.z += p1*vv.z; a1.w += p1*vv.w;
            }
            *(float4*)&tmp_s[i0*68 + h*32 + d0]     = a0;
            *(float4*)&tmp_s[(i0+1)*68 + h*32 + d0] = a1;
        }
        __syncthreads();
    }

    // Wo transposed into kt region: wot[e][jo] pitch 68
    float* wot = kt_s;
    for (int i = t; i < 4096; i += 256) {
        int jo = i >> 6, e = i & 63;
        wot[e*68 + jo] = Wo[i];
    }
    __syncthreads();

    // out projection + raw-reshape residual
    {
        int j0 = (t & 7) * 8;
        int nl = (t >> 3) * 2;
        float4 b0 = *(const float4*)&bo[j0];
        float4 b1 = *(const float4*)&bo[j0 + 4];
        float4 a00 = b0, a01 = b1, a10 = b0, a11 = b1;
        for (int e = 0; e < 64; e++) {
            float t0 = tmp_s[nl*68 + e];
            float t1 = tmp_s[(nl+1)*68 + e];
            float4 w0 = *(float4*)&wot[e*68 + j0];
            float4 w1 = *(float4*)&wot[e*68 + j0 + 4];
            a00.x += t0*w0.x; a00.y += t0*w0.y; a00.z += t0*w0.z; a00.w += t0*w0.w;
            a01.x += t0*w1.x; a01.y += t0*w1.y; a01.z += t0*w1.z; a01.w += t0*w1.w;
            a10.x += t1*w0.x; a10.y += t1*w0.y; a10.z += t1*w0.z; a10.w += t1*w0.w;
            a11.x += t1*w1.x; a11.y += t1*w1.y; a11.z += t1*w1.z; a11.w += t1*w1.w;
        }
        // flat index within batch: p = (n0+nl)*64 + j0  (raw reshape semantics)
        size_t p0 = (size_t)(n0 + nl) * 64 + j0;
        size_t p1 = p0 + 64;
        float4 r;
        float* ob = out + (size_t)b * DN;
        r = *(const float4*)&xb[p0];     a00.x+=r.x; a00.y+=r.y; a00.z+=r.z; a00.w+=r.w;
        r = *(const float4*)&xb[p0 + 4]; a01.x+=r.x; a01.y+=r.y; a01.z+=r.z; a01.w+=r.w;
        r = *(const float4*)&xb[p1];     a10.x+=r.x; a10.y+=r.y; a10.z+=r.z; a10.w+=r.w;
        r = *(const float4*)&xb[p1 + 4]; a11.x+=r.x; a11.y+=r.y; a11.z+=r.z; a11.w+=r.w;
        *(float4*)&ob[p0]     = a00;
        *(float4*)&ob[p0 + 4] = a01;
        *(float4*)&ob[p1]     = a10;
        *(float4*)&ob[p1 + 4] = a11;
    }
}

// ---------------- launch ----------------
extern "C" void kernel_launch(void* const* d_in, const int* in_sizes, int n_in,
                              void* d_out, int out_size) {
    const float* x    = (const float*)d_in[0];
    const float* W_dw = (const float*)d_in[1];
    const float* b_dw = (const float*)d_in[2];
    const float* Wq   = (const float*)d_in[3];
    const float* bq   = (const float*)d_in[4];
    const float* Wk   = (const float*)d_in[5];
    const float* bk   = (const float*)d_in[6];
    const float* Wv   = (const float*)d_in[7];
    const float* bv   = (const float*)d_in[8];
    const float* Wo   = (const float*)d_in[9];
    const float* bo   = (const float*)d_in[10];
    const float* Bb   = (const float*)d_in[11];
    float* out = (float*)d_out;

    const int smem_k2 = (256*68 + 64*68*2 + 1024 + 4*4096) * 4;   // 174080 B
    const int smem_k3 = 42304 * 4;                                 // 169216 B
    cudaFuncSetAttribute(kv_kernel,   cudaFuncAttributeMaxDynamicSharedMemorySize, smem_k2);
    cudaFuncSetAttribute(attn_kernel, cudaFuncAttributeMaxDynamicSharedMemorySize, smem_k3);

    ln_stats_kernel<<<B_SZ, 512>>>(x);
    kv_kernel<<<B_SZ, 256, smem_k2>>>(x, W_dw, b_dw, Wk, bk, Wv, bv);
    attn_kernel<<<dim3(64, B_SZ), 256, smem_k3>>>(x, Wq, bq, Wo, bo, Bb, out);
}

// round 3
// speedup vs baseline: 1.0181x; 1.0181x over previous
#include <cuda_runtime.h>
#include <math.h>

#define B_SZ 32
#define D    64
#define HWD  64
#define NQ   4096
#define MKV  256
#define HEADS 2
#define DKH  32
#define DVH  32
#define DN   (D*NQ)   // 262144 per batch

// ---------------- scratch (no allocation allowed) ----------------
__device__ float g_stats[2 * B_SZ];                    // mu, rstd per batch
__device__ float g_K[B_SZ * HEADS * DKH * MKV];        // [b][h][d][j]
__device__ float g_V[B_SZ * HEADS * MKV * DVH];        // [b][h][j][d]

// ---------------- kernel 1: layernorm stats ----------------
__global__ void ln_stats_kernel(const float* __restrict__ x) {
    int b = blockIdx.x;
    const float4* xb = (const float4*)(x + (size_t)b * DN);
    float s1 = 0.f, s2 = 0.f;
    for (int i = threadIdx.x; i < DN / 4; i += blockDim.x) {
        float4 v = xb[i];
        s1 += v.x + v.y + v.z + v.w;
        s2 += v.x*v.x + v.y*v.y + v.z*v.z + v.w*v.w;
    }
    #pragma unroll
    for (int o = 16; o > 0; o >>= 1) {
        s1 += __shfl_xor_sync(~0u, s1, o);
        s2 += __shfl_xor_sync(~0u, s2, o);
    }
    __shared__ float r1[32], r2[32];
    int wid = threadIdx.x >> 5, lid = threadIdx.x & 31;
    if (lid == 0) { r1[wid] = s1; r2[wid] = s2; }
    __syncthreads();
    if (threadIdx.x == 0) {
        float t1 = 0.f, t2 = 0.f;
        int nw = blockDim.x >> 5;
        for (int i = 0; i < nw; i++) { t1 += r1[i]; t2 += r2[i]; }
        float inv = 1.f / (float)DN;
        float mu  = t1 * inv;
        float var = t2 * inv - mu * mu;
        g_stats[2*b]   = mu;
        g_stats[2*b+1] = rsqrtf(var + 1e-5f);
    }
}

// ---------------- kernel 2: dw-conv + K/V projections ----------------
// smem: kv[256][68], Wks[64][68], Wvs[64][68], Wdws[64][16], xs[4][4096]
__global__ void __launch_bounds__(256) kv_kernel(
    const float* __restrict__ x, const float* __restrict__ W_dw,
    const float* __restrict__ b_dw,
    const float* __restrict__ Wk, const float* __restrict__ bk,
    const float* __restrict__ Wv, const float* __restrict__ bv)
{
    int b = blockIdx.x;
    int t = threadIdx.x;
    extern __shared__ float sm[];
    float* kv   = sm;                  // 256*68 = 17408
    float* Wks  = kv + 256*68;         // 4352
    float* Wvs  = Wks + 64*68;         // 4352
    float* Wdws = Wvs + 64*68;         // 1024
    float* xs   = Wdws + 1024;         // 16384

    for (int i = t; i < 64*64; i += 256) {
        int e = i >> 6, c = i & 63;
        Wks[e*68 + c] = Wk[i];
        Wvs[e*68 + c] = Wv[i];
    }
    for (int i = t; i < 1024; i += 256) Wdws[i] = W_dw[i];

    int ky = t >> 4, kx = t & 15;   // m = t = ky*16 + kx
    const float* xb = x + (size_t)b * DN;

    for (int cc = 0; cc < 64; cc += 4) {
        __syncthreads();
        for (int i = t*4; i < 4*4096; i += 256*4)
            *(float4*)&xs[i] = *(const float4*)&xb[cc*4096 + i];
        __syncthreads();
        #pragma unroll
        for (int cl = 0; cl < 4; cl++) {
            float acc = b_dw[cc + cl];
            const float* xr = &xs[cl*4096 + ky*256 + kx*4];
            const float* wr = &Wdws[(cc + cl)*16];
            #pragma unroll
            for (int sy = 0; sy < 4; sy++)
                #pragma unroll
                for (int sx = 0; sx < 4; sx++)
                    acc += xr[sy*64 + sx] * wr[sy*4 + sx];
            kv[t*68 + cc + cl] = acc;
        }
    }
    __syncthreads();

    int mg = t & 31;
    int e0 = (t >> 5) * 8;
    float acc[8][8];

    // ---- K projection ----
    #pragma unroll
    for (int ee = 0; ee < 8; ee++) {
        float bias = bk[e0 + ee];
        #pragma unroll
        for (int mm = 0; mm < 8; mm++) acc[mm][ee] = bias;
    }
    for (int c = 0; c < 64; c += 4) {
        float4 kvv[8], wv[8];
        #pragma unroll
        for (int mm = 0; mm < 8; mm++) kvv[mm] = *(float4*)&kv[(mg + 32*mm)*68 + c];
        #pragma unroll
        for (int ee = 0; ee < 8; ee++) wv[ee] = *(float4*)&Wks[(e0 + ee)*68 + c];
        #pragma unroll
        for (int mm = 0; mm < 8; mm++)
            #pragma unroll
            for (int ee = 0; ee < 8; ee++)
                acc[mm][ee] += kvv[mm].x*wv[ee].x + kvv[mm].y*wv[ee].y
                             + kvv[mm].z*wv[ee].z + kvv[mm].w*wv[ee].w;
    }
    #pragma unroll
    for (int ee = 0; ee < 8; ee++) {
        int e = e0 + ee, h = e >> 5, d = e & 31;
        float* dst = &g_K[(((size_t)b*HEADS + h)*DKH + d)*MKV];
        #pragma unroll
        for (int mm = 0; mm < 8; mm++) dst[mg + 32*mm] = acc[mm][ee];
    }

    // ---- V projection ----
    #pragma unroll
    for (int ee = 0; ee < 8; ee++) {
        float bias = bv[e0 + ee];
        #pragma unroll
        for (int mm = 0; mm < 8; mm++) acc[mm][ee] = bias;
    }
    for (int c = 0; c < 64; c += 4) {
        float4 kvv[8], wv[8];
        #pragma unroll
        for (int mm = 0; mm < 8; mm++) kvv[mm] = *(float4*)&kv[(mg + 32*mm)*68 + c];
        #pragma unroll
        for (int ee = 0; ee < 8; ee++) wv[ee] = *(float4*)&Wvs[(e0 + ee)*68 + c];
        #pragma unroll
        for (int mm = 0; mm < 8; mm++)
            #pragma unroll
            for (int ee = 0; ee < 8; ee++)
                acc[mm][ee] += kvv[mm].x*wv[ee].x + kvv[mm].y*wv[ee].y
                             + kvv[mm].z*wv[ee].z + kvv[mm].w*wv[ee].w;
    }
    #pragma unroll
    for (int ee = 0; ee < 8; ee++) {
        int e = e0 + ee, h = e >> 5, d = e & 31;
        #pragma unroll
        for (int mm = 0; mm < 8; mm++)
            g_V[(((size_t)b*HEADS + h)*MKV + (mg + 32*mm))*DVH + d] = acc[mm][ee];
    }
}

// ---------------- kernel 3: fused LN + Qproj + attention + out proj ----------------
// smem layout (floats):
//   q_s   @ 0      [64][65]   = 4160
//   p_s   @ 4160   [64][256]  = 16384   (phase1 alias: xn_s [64][65])
//   kt_s  @ 20544  [32][256]  = 8192    (phase1 alias: Wq_s [64][68]; phase3: Wot [64][68])
//   v_s   @ 28736  [256][36]  = 9216
//   tmp_s @ 37952  [64][68]   = 4352
//   total 42304 floats = 169216 B
__global__ void __launch_bounds__(256) attn_kernel(
    const float* __restrict__ x,
    const float* __restrict__ Wq, const float* __restrict__ bq,
    const float* __restrict__ Wo, const float* __restrict__ bo,
    const float* __restrict__ Bbias,
    float* __restrict__ out)
{
    int b  = blockIdx.y;
    int n0 = blockIdx.x * 64;
    int t  = threadIdx.x;
    int lane = t & 31, w = t >> 5;

    extern __shared__ float sm[];
    float* q_s   = sm;
    float* p_s   = sm + 4160;
    float* xn_s  = p_s;
    float* kt_s  = sm + 20544;
    float* v_s   = sm + 28736;
    float* tmp_s = sm + 37952;

    float mu = g_stats[2*b], rstd = g_stats[2*b+1];
    const float* xb = x + (size_t)b * DN;

    // Wq into kt region ([e][c] pitch 68)
    float* wq_s = kt_s;
    for (int i = t; i < 4096; i += 256) {
        int e = i >> 6, c = i & 63;
        wq_s[e*68 + c] = Wq[i];
    }
    // normalized x tile: xn_s[query][c], pitch 65 (conflict-free transpose writes)
    for (int i = t; i < 4096; i += 256) {
        int c = i >> 6, col = i & 63;
        float v = xb[c*4096 + n0 + col];
        xn_s[col*65 + c] = (v - mu) * rstd;
    }
    __syncthreads();

    // Q projection: thread -> (query i = t&63, 16 outputs e0..e0+15)
    {
        int qi = t & 63;
        int e0 = (t >> 6) * 16;
        float acc[16];
        #pragma unroll
        for (int ee = 0; ee < 16; ee++) acc[ee] = bq[e0 + ee];
        for (int c = 0; c < 64; c += 4) {
            float xv0 = xn_s[qi*65 + c + 0];
            float xv1 = xn_s[qi*65 + c + 1];
            float xv2 = xn_s[qi*65 + c + 2];
            float xv3 = xn_s[qi*65 + c + 3];
            #pragma unroll
            for (int ee = 0; ee < 16; ee++) {
                float4 wv = *(float4*)&wq_s[(e0 + ee)*68 + c];
                acc[ee] += xv0*wv.x + xv1*wv.y + xv2*wv.z + xv3*wv.w;
            }
        }
        #pragma unroll
        for (int ee = 0; ee < 16; ee++) q_s[qi*65 + e0 + ee] = acc[ee];
    }
    __syncthreads();

    const float scale = 0.17677669529663687f;   // 32^-0.5
    const float LOG2E = 1.4426950408889634f;

    for (int h = 0; h < HEADS; h++) {
        // stage K^T [d][j] and V [j][d]
        const float* Kg = &g_K[((size_t)b*HEADS + h)*DKH*MKV];
        const float* Vg = &g_V[((size_t)b*HEADS + h)*MKV*DVH];
        for (int i = t; i < DKH*MKV; i += 256) kt_s[i] = Kg[i];
        for (int i = t; i < MKV*DVH; i += 256) {
            int j = i >> 5, d = i & 31;
            v_s[j*36 + d] = Vg[i];
        }
        __syncthreads();

        // QK: warp w owns queries [8w, 8w+8); lane owns j = lane + 32*jj
        float s[8][8];
        #pragma unroll
        for (int ii = 0; ii < 8; ii++)
            #pragma unroll
            for (int jj = 0; jj < 8; jj++) s[ii][jj] = 0.f;

        for (int d = 0; d < 32; d++) {
            float kr[8], qr[8];
            #pragma unroll
            for (int jj = 0; jj < 8; jj++) kr[jj] = kt_s[d*256 + lane + 32*jj];
            #pragma unroll
            for (int ii = 0; ii < 8; ii++) qr[ii] = q_s[(8*w + ii)*65 + h*32 + d];
            #pragma unroll
            for (int ii = 0; ii < 8; ii++)
                #pragma unroll
                for (int jj = 0; jj < 8; jj++) s[ii][jj] += qr[ii] * kr[jj];
        }

        // bias + softmax (register rows, warp butterfly)
        const float* Bp = Bbias + ((size_t)(h*NQ + n0 + 8*w))*MKV + lane;
        #pragma unroll
        for (int ii = 0; ii < 8; ii++) {
            #pragma unroll
            for (int jj = 0; jj < 8; jj++)
                s[ii][jj] = fmaf(s[ii][jj], scale, Bp[ii*MKV + 32*jj]);
            float mx = s[ii][0];
            #pragma unroll
            for (int jj = 1; jj < 8; jj++) mx = fmaxf(mx, s[ii][jj]);
            #pragma unroll
            for (int o = 16; o > 0; o >>= 1) mx = fmaxf(mx, __shfl_xor_sync(~0u, mx, o));
            float sum = 0.f;
            #pragma unroll
            for (int jj = 0; jj < 8; jj++) {
                s[ii][jj] = exp2f((s[ii][jj] - mx) * LOG2E);
                sum += s[ii][jj];
            }
            #pragma unroll
            for (int o = 16; o > 0; o >>= 1) sum += __shfl_xor_sync(~0u, sum, o);
            float inv = __fdividef(1.f, sum);
            #pragma unroll
            for (int jj = 0; jj < 8; jj++)
                p_s[(8*w + ii)*256 + lane + 32*jj] = s[ii][jj] * inv;
        }
        __syncthreads();

        // AV: thread -> (2 queries i0,i0+1) x (4 dims d0..d0+3)
        {
            int d0 = (t & 7) * 4;
            int i0 = (t >> 3) * 2;
            float4 a0 = {0,0,0,0}, a1 = {0,0,0,0};
            #pragma unroll 4
            for (int j = 0; j < 256; j++) {
                float p0 = p_s[i0*256 + j];
                float p1 = p_s[(i0+1)*256 + j];
                float4 vv = *(float4*)&v_s[j*36 + d0];
                a0.x += p0*vv.x; a0.y += p0*vv.y; a0.z += p0*vv.z; a0.w += p0*vv.w;
                a1.x += p1*vv.x; a1.y += p1*vv.y; a1.z += p1*vv.z; a1.w += p1*vv.w;
            }
            *(float4*)&tmp_s[i0*68 + h*32 + d0]     = a0;
            *(float4*)&tmp_s[(i0+1)*68 + h*32 + d0] = a1;
        }
        __syncthreads();
    }

    // Wo transposed into kt region: wot[e][jo] pitch 68
    float* wot = kt_s;
    for (int i = t; i < 4096; i += 256) {
        int jo = i >> 6, e = i & 63;
        wot[e*68 + jo] = Wo[i];
    }
    __syncthreads();

    // out projection + raw-reshape residual
    {
        int j0 = (t & 7) * 8;
        int nl = (t >> 3) * 2;
        float4 b0 = *(const float4*)&bo[j0];
        float4 b1 = *(const float4*)&bo[j0 + 4];
        float4 a00 = b0, a01 = b1, a10 = b0, a11 = b1;
        for (int e = 0; e < 64; e++) {
            float t0 = tmp_s[nl*68 + e];
            float t1 = tmp_s[(nl+1)*68 + e];
            float4 w0 = *(float4*)&wot[e*68 + j0];
            float4 w1 = *(float4*)&wot[e*68 + j0 + 4];
            a00.x += t0*w0.x; a00.y += t0*w0.y; a00.z += t0*w0.z; a00.w += t0*w0.w;
            a01.x += t0*w1.x; a01.y += t0*w1.y; a01.z += t0*w1.z; a01.w += t0*w1.w;
            a10.x += t1*w0.x; a10.y += t1*w0.y; a10.z += t1*w0.z; a10.w += t1*w0.w;
            a11.x += t1*w1.x; a11.y += t1*w1.y; a11.z += t1*w1.z; a11.w += t1*w1.w;
        }
        // flat index within batch: p = (n0+nl)*64 + j0  (raw reshape semantics)
        size_t p0 = (size_t)(n0 + nl) * 64 + j0;
        size_t p1 = p0 + 64;
        float4 r;
        float* ob = out + (size_t)b * DN;
        r = *(const float4*)&xb[p0];     a00.x+=r.x; a00.y+=r.y; a00.z+=r.z; a00.w+=r.w;
        r = *(const float4*)&xb[p0 + 4]; a01.x+=r.x; a01.y+=r.y; a01.z+=r.z; a01.w+=r.w;
        r = *(const float4*)&xb[p1];     a10.x+=r.x; a10.y+=r.y; a10.z+=r.z; a10.w+=r.w;
        r = *(const float4*)&xb[p1 + 4]; a11.x+=r.x; a11.y+=r.y; a11.z+=r.z; a11.w+=r.w;
        *(float4*)&ob[p0]     = a00;
        *(float4*)&ob[p0 + 4] = a01;
        *(float4*)&ob[p1]     = a10;
        *(float4*)&ob[p1 + 4] = a11;
    }
}

// ---------------- launch ----------------
extern "C" void kernel_launch(void* const* d_in, const int* in_sizes, int n_in,
                              void* d_out, int out_size) {
    const float* x    = (const float*)d_in[0];
    const float* W_dw = (const float*)d_in[1];
    const float* b_dw = (const float*)d_in[2];
    const float* Wq   = (const float*)d_in[3];
    const float* bq   = (const float*)d_in[4];
    const float* Wk   = (const float*)d_in[5];
    const float* bk   = (const float*)d_in[6];
    const float* Wv   = (const float*)d_in[7];
    const float* bv   = (const float*)d_in[8];
    const float* Wo   = (const float*)d_in[9];
    const float* bo   = (const float*)d_in[10];
    const float* Bb   = (const float*)d_in[11];
    float* out = (float*)d_out;

    const int smem_k2 = (256*68 + 64*68*2 + 1024 + 4*4096) * 4;   // 174080 B
    const int smem_k3 = 42304 * 4;                                 // 169216 B
    cudaFuncSetAttribute(kv_kernel,   cudaFuncAttributeMaxDynamicSharedMemorySize, smem_k2);
    cudaFuncSetAttribute(attn_kernel, cudaFuncAttributeMaxDynamicSharedMemorySize, smem_k3);

    ln_stats_kernel<<<B_SZ, 512>>>(x);
    kv_kernel<<<B_SZ, 256, smem_k2>>>(x, W_dw, b_dw, Wk, bk, Wv, bv);
    attn_kernel<<<dim3(64, B_SZ), 256, smem_k3>>>(x, Wq, bq, Wo, bo, Bb, out);
}

// round 9
// speedup vs baseline: 3.1668x; 3.1105x over previous
#include <cuda_runtime.h>
#include <cuda_bf16.h>
#include <cstdint>
#include <math.h>

#define B_SZ 32
#define NQ   4096
#define MKV  256
#define DN   (64*NQ)

__device__ float g_stats[2*B_SZ];
__device__ float g_part[B_SZ*8*2];
__device__ float g_K[B_SZ*2*MKV*32];   // [b][h][j][d]
__device__ float g_V[B_SZ*2*32*MKV];   // [b][h][d][j]

__device__ __forceinline__ uint32_t smem_u32(const void* p){
    uint32_t a;
    asm("{ .reg .u64 t; cvta.to.shared.u64 t, %1; cvt.u32.u64 %0, t; }" : "=r"(a) : "l"(p));
    return a;
}
__device__ __forceinline__ float ex2f_(float v){
    float r; asm("ex2.approx.ftz.f32 %0, %1;" : "=f"(r) : "f"(v)); return r;
}
__device__ __forceinline__ void ldsm4(uint32_t addr, uint32_t r[4]){
    asm volatile("ldmatrix.sync.aligned.m8n8.x4.shared.b16 {%0,%1,%2,%3}, [%4];"
        : "=r"(r[0]),"=r"(r[1]),"=r"(r[2]),"=r"(r[3]) : "r"(addr));
}
__device__ __forceinline__ void ldsm2(uint32_t addr, uint32_t r[2]){
    asm volatile("ldmatrix.sync.aligned.m8n8.x2.shared.b16 {%0,%1}, [%2];"
        : "=r"(r[0]),"=r"(r[1]) : "r"(addr));
}
__device__ __forceinline__ void mma_bf16(float c[4], const uint32_t a[4], const uint32_t b[2]){
    asm volatile("mma.sync.aligned.m16n8k16.row.col.f32.bf16.bf16.f32 "
        "{%0,%1,%2,%3}, {%4,%5,%6,%7}, {%8,%9}, {%0,%1,%2,%3};"
        : "+f"(c[0]),"+f"(c[1]),"+f"(c[2]),"+f"(c[3])
        : "r"(a[0]),"r"(a[1]),"r"(a[2]),"r"(a[3]), "r"(b[0]),"r"(b[1]));
}
__device__ __forceinline__ uint32_t packbf(float a, float b){
    __nv_bfloat162 h = __floats2bfloat162_rn(a, b);
    return *(uint32_t*)&h;
}

// ---------- kernel 1: LN stats ----------
__global__ void ln_partial_kernel(const float* __restrict__ x){
    int b = blockIdx.x, p = blockIdx.y;
    const float4* xb = (const float4*)(x + (size_t)b*DN + (size_t)p*(DN/8));
    float s1=0.f, s2=0.f;
    for (int i = threadIdx.x; i < DN/32; i += blockDim.x){
        float4 v = xb[i];
        s1 += v.x+v.y+v.z+v.w; s2 += v.x*v.x+v.y*v.y+v.z*v.z+v.w*v.w;
    }
    #pragma unroll
    for (int o=16;o>0;o>>=1){ s1+=__shfl_xor_sync(~0u,s1,o); s2+=__shfl_xor_sync(~0u,s2,o); }
    __shared__ float r1[8], r2[8];
    int wid = threadIdx.x>>5, lid = threadIdx.x&31;
    if (lid==0){ r1[wid]=s1; r2[wid]=s2; }
    __syncthreads();
    if (threadIdx.x==0){
        float t1=0.f,t2=0.f;
        for (int i=0;i<(int)(blockDim.x>>5);i++){ t1+=r1[i]; t2+=r2[i]; }
        g_part[(b*8+p)*2]=t1; g_part[(b*8+p)*2+1]=t2;
    }
}
__global__ void ln_final_kernel(){
    int b = threadIdx.x;
    if (b < B_SZ){
        float t1=0.f,t2=0.f;
        for (int p=0;p<8;p++){ t1+=g_part[(b*8+p)*2]; t2+=g_part[(b*8+p)*2+1]; }
        float inv = 1.f/(float)DN, mu = t1*inv, var = t2*inv - mu*mu;
        g_stats[2*b]=mu; g_stats[2*b+1]=rsqrtf(var+1e-5f);
    }
}

// ---------- kernel 2: dw-conv + K/V proj ----------
__global__ void __launch_bounds__(256) kv_kernel(
    const float* __restrict__ x, const float* __restrict__ W_dw, const float* __restrict__ b_dw,
    const float* __restrict__ Wk, const float* __restrict__ bk,
    const float* __restrict__ Wv, const float* __restrict__ bv)
{
    int b = blockIdx.x, t = threadIdx.x;
    extern __shared__ float sm[];
    float* kv = sm;
    float* Wks = kv+256*68;  float* Wvs = Wks+64*68;
    float* Wdws = Wvs+64*68; float* xs = Wdws+1024;

    for (int i=t;i<64*64;i+=256){ int e=i>>6,c=i&63; Wks[e*68+c]=Wk[i]; Wvs[e*68+c]=Wv[i]; }
    for (int i=t;i<1024;i+=256) Wdws[i]=W_dw[i];
    int ky=t>>4, kx=t&15;
    const float* xb = x + (size_t)b*DN;
    for (int cc=0;cc<64;cc+=4){
        __syncthreads();
        for (int i=t*4;i<4*4096;i+=1024) *(float4*)&xs[i]=*(const float4*)&xb[cc*4096+i];
        __syncthreads();
        #pragma unroll
        for (int cl=0;cl<4;cl++){
            float acc=b_dw[cc+cl];
            const float* xr=&xs[cl*4096+ky*256+kx*4];
            const float* wr=&Wdws[(cc+cl)*16];
            #pragma unroll
            for (int sy=0;sy<4;sy++)
                #pragma unroll
                for (int sx=0;sx<4;sx++) acc += xr[sy*64+sx]*wr[sy*4+sx];
            kv[t*68+cc+cl]=acc;
        }
    }
    __syncthreads();
    int mg=t&31, e0=(t>>5)*8;
    float acc[8][8];
    #pragma unroll
    for (int ee=0;ee<8;ee++){ float bb=bk[e0+ee]; for (int mm=0;mm<8;mm++) acc[mm][ee]=bb; }
    for (int c=0;c<64;c+=4){
        float4 kvv[8],wv[8];
        #pragma unroll
        for (int mm=0;mm<8;mm++) kvv[mm]=*(float4*)&kv[(mg+32*mm)*68+c];
        #pragma unroll
        for (int ee=0;ee<8;ee++) wv[ee]=*(float4*)&Wks[(e0+ee)*68+c];
        #pragma unroll
        for (int mm=0;mm<8;mm++)
            #pragma unroll
            for (int ee=0;ee<8;ee++)
                acc[mm][ee]+=kvv[mm].x*wv[ee].x+kvv[mm].y*wv[ee].y+kvv[mm].z*wv[ee].z+kvv[mm].w*wv[ee].w;
    }
    #pragma unroll
    for (int ee=0;ee<8;ee++){
        int e=e0+ee, h=e>>5, d=e&31;
        #pragma unroll
        for (int mm=0;mm<8;mm++) g_K[((size_t)(b*2+h)*256+(mg+32*mm))*32+d]=acc[mm][ee];
    }
    #pragma unroll
    for (int ee=0;ee<8;ee++){ float bb=bv[e0+ee]; for (int mm=0;mm<8;mm++) acc[mm][ee]=bb; }
    for (int c=0;c<64;c+=4){
        float4 kvv[8],wv[8];
        #pragma unroll
        for (int mm=0;mm<8;mm++) kvv[mm]=*(float4*)&kv[(mg+32*mm)*68+c];
        #pragma unroll
        for (int ee=0;ee<8;ee++) wv[ee]=*(float4*)&Wvs[(e0+ee)*68+c];
        #pragma unroll
        for (int mm=0;mm<8;mm++)
            #pragma unroll
            for (int ee=0;ee<8;ee++)
                acc[mm][ee]+=kvv[mm].x*wv[ee].x+kvv[mm].y*wv[ee].y+kvv[mm].z*wv[ee].z+kvv[mm].w*wv[ee].w;
    }
    #pragma unroll
    for (int ee=0;ee<8;ee++){
        int e=e0+ee, h=e>>5, d=e&31;
        #pragma unroll
        for (int mm=0;mm<8;mm++) g_V[((size_t)(b*2+h)*32+d)*256+(mg+32*mm)]=acc[mm][ee];
    }
}

// ---------- kernel 3: mma.sync bf16 attention ----------
#define XN_OFF 0
#define Q_OFF  18432
#define WQ_OFF 36864
#define WO_OFF 46080
#define K_OFF  55296
#define V_OFF  96256
#define P_OFF  130048
__global__ void __launch_bounds__(256, 1) attn_kernel(
    const float* __restrict__ x,
    const float* __restrict__ Wq, const float* __restrict__ bq,
    const float* __restrict__ Wo, const float* __restrict__ bo,
    const float* __restrict__ Bbias, float* __restrict__ out)
{
    int b = blockIdx.x, n0 = blockIdx.y*128, t = threadIdx.x;
    int w = t>>5, ln = t&31;
    int r = ln>>2, cq = (ln&3)*2;
    int row0 = 16*w;

    extern __shared__ char smraw[];
    uint32_t sb = smem_u32(smraw);
    __nv_bfloat16* XN = (__nv_bfloat16*)(smraw + XN_OFF);
    __nv_bfloat16* Qs = (__nv_bfloat16*)(smraw + Q_OFF);
    __nv_bfloat16* WQs = (__nv_bfloat16*)(smraw + WQ_OFF);
    __nv_bfloat16* WOs = (__nv_bfloat16*)(smraw + WO_OFF);
    __nv_bfloat16* Ks = (__nv_bfloat16*)(smraw + K_OFF);
    __nv_bfloat16* Vs = (__nv_bfloat16*)(smraw + V_OFF);
    __nv_bfloat16* Ps = (__nv_bfloat16*)(smraw + P_OFF);
    float* bqs = (float*)(smraw + 197632);
    float* bos = (float*)(smraw + 197888);

    float mu = g_stats[2*b], rstd = g_stats[2*b+1];
    const float* xb = x + (size_t)b*DN;

    // ---- staging ----
    for (int i=t;i<8192;i+=256){
        int c=i>>7, nl=i&127;
        XN[nl*72+c] = __float2bfloat16((xb[(size_t)c*4096 + n0 + nl]-mu)*rstd);
    }
    for (int i=t;i<4096;i+=256){
        int e=i>>6, c=i&63;
        WQs[e*72+c] = __float2bfloat16(Wq[i]);
        WOs[e*72+c] = __float2bfloat16(Wo[i]);   // [cout][e] row-major as-is
    }
    for (int i=t;i<16384;i+=256){
        int hh=i>>13, rr=i&8191;
        int j=rr>>5, d=rr&31;
        Ks[hh*10240 + j*40 + d] = __float2bfloat16(g_K[(size_t)(b*2+hh)*8192 + rr]);
    }
    for (int i=t;i<16384;i+=256){
        int hh=i>>13, rr=i&8191;
        int d=rr>>8, j=rr&255;
        Vs[hh*8448 + d*264 + j] = __float2bfloat16(g_V[(size_t)(b*2+hh)*8192 + rr]);
    }
    if (t<64){ bqs[t]=bq[t]; bos[t]=bo[t]; }
    __syncthreads();

    uint32_t u_xn = sb + XN_OFF, u_q = sb + Q_OFF, u_wq = sb + WQ_OFF, u_wo = sb + WO_OFF;
    uint32_t u_k = sb + K_OFF, u_v = sb + V_OFF, u_p = sb + P_OFF;
    int a_row = row0 + (t&15);
    int a_cb = ((t>>4)&1)*16;        // FIX: lane bit 4, not thread>>4
    int b_row = t&7;
    int b_cb = ((t>>3)&1)*16;

    // ---- Q projection: Q = XN @ Wq^T + bq ----
    {
        float qa[8][4];
        #pragma unroll
        for (int j=0;j<8;j++){ qa[j][0]=0;qa[j][1]=0;qa[j][2]=0;qa[j][3]=0; }
        #pragma unroll
        for (int kt=0;kt<4;kt++){
            uint32_t a4[4];
            ldsm4(u_xn + a_row*144 + a_cb + kt*32, a4);
            #pragma unroll
            for (int j=0;j<8;j++){
                uint32_t b2[2];
                ldsm2(u_wq + (8*j+b_row)*144 + b_cb + kt*32, b2);
                mma_bf16(qa[j], a4, b2);
            }
        }
        #pragma unroll
        for (int j=0;j<8;j++){
            int col = 8*j + cq;
            float b0 = bqs[col], b1 = bqs[col+1];
            *(uint32_t*)&Qs[(row0+r)*72 + col]   = packbf(qa[j][0]+b0, qa[j][1]+b1);
            *(uint32_t*)&Qs[(row0+r+8)*72 + col] = packbf(qa[j][2]+b0, qa[j][3]+b1);
        }
        __syncwarp();
    }

    const float C1 = 0.17677669529663687f*1.4426950408889634f;
    const float C2 = 1.4426950408889634f;

    // ---- per head: QK -> softmax -> AV ----
    for (int h=0; h<2; h++){
        float psum0 = 0.f, psum1 = 0.f;
        #pragma unroll 1
        for (int ch=0; ch<2; ch++){
            float sa[16][4];
            #pragma unroll
            for (int j=0;j<16;j++){ sa[j][0]=0;sa[j][1]=0;sa[j][2]=0;sa[j][3]=0; }
            #pragma unroll
            for (int kt=0;kt<2;kt++){
                uint32_t a4[4];
                ldsm4(u_q + a_row*144 + h*64 + a_cb + kt*32, a4);
                #pragma unroll
                for (int j=0;j<16;j++){
                    uint32_t b2[2];
                    ldsm2(u_k + h*20480 + (128*ch + 8*j + b_row)*80 + b_cb + kt*32, b2);
                    mma_bf16(sa[j], a4, b2);
                }
            }
            const float* Bg = Bbias + (size_t)(h*NQ + n0 + row0 + r)*MKV + 128*ch + cq;
            #pragma unroll
            for (int j=0;j<16;j++){
                float2 bA = *(const float2*)&Bg[8*j];
                float2 bB = *(const float2*)&Bg[8*j + 8*MKV];
                float p0 = ex2f_(fmaf(sa[j][0], C1, bA.x*C2));
                float p1 = ex2f_(fmaf(sa[j][1], C1, bA.y*C2));
                float p2 = ex2f_(fmaf(sa[j][2], C1, bB.x*C2));
                float p3 = ex2f_(fmaf(sa[j][3], C1, bB.y*C2));
                psum0 += p0+p1; psum1 += p2+p3;
                int col = 128*ch + 8*j + cq;
                *(uint32_t*)&Ps[(row0+r)*264 + col]   = packbf(p0, p1);
                *(uint32_t*)&Ps[(row0+r+8)*264 + col] = packbf(p2, p3);
            }
            __syncwarp();
        }
        // AV
        float oacc[4][4];
        #pragma unroll
        for (int j=0;j<4;j++){ oacc[j][0]=0;oacc[j][1]=0;oacc[j][2]=0;oacc[j][3]=0; }
        #pragma unroll 4
        for (int kt=0;kt<16;kt++){
            uint32_t a4[4];
            ldsm4(u_p + a_row*528 + a_cb + kt*32, a4);
            #pragma unroll
            for (int j=0;j<4;j++){
                uint32_t b2[2];
                ldsm2(u_v + h*16896 + (8*j+b_row)*528 + b_cb + kt*32, b2);
                mma_bf16(oacc[j], a4, b2);
            }
        }
        psum0 += __shfl_xor_sync(~0u, psum0, 1);
        psum0 += __shfl_xor_sync(~0u, psum0, 2);
        psum1 += __shfl_xor_sync(~0u, psum1, 1);
        psum1 += __shfl_xor_sync(~0u, psum1, 2);
        float inv0 = __fdividef(1.f, psum0), inv1 = __fdividef(1.f, psum1);
        #pragma unroll
        for (int j=0;j<4;j++){
            int col = h*32 + 8*j + cq;
            *(uint32_t*)&XN[(row0+r)*72 + col]   = packbf(oacc[j][0]*inv0, oacc[j][1]*inv0);
            *(uint32_t*)&XN[(row0+r+8)*72 + col] = packbf(oacc[j][2]*inv1, oacc[j][3]*inv1);
        }
        __syncwarp();
    }

    // ---- out projection + epilogue ----
    {
        float fa[8][4];
        #pragma unroll
        for (int j=0;j<8;j++){ fa[j][0]=0;fa[j][1]=0;fa[j][2]=0;fa[j][3]=0; }
        #pragma unroll
        for (int kt=0;kt<4;kt++){
            uint32_t a4[4];
            ldsm4(u_xn + a_row*144 + a_cb + kt*32, a4);
            #pragma unroll
            for (int j=0;j<8;j++){
                uint32_t b2[2];
                ldsm2(u_wo + (8*j+b_row)*144 + b_cb + kt*32, b2);
                mma_bf16(fa[j], a4, b2);
            }
        }
        size_t base0 = (size_t)b*DN + (size_t)(n0+row0+r)*64;
        size_t base1 = base0 + 8*64;
        #pragma unroll
        for (int j=0;j<8;j++){
            int col = 8*j + cq;
            float b0 = bos[col], b1 = bos[col+1];
            float2 x0 = *(const float2*)&x[base0 + col];
            float2 x1 = *(const float2*)&x[base1 + col];
            float2 o0 = { fa[j][0]+b0+x0.x, fa[j][1]+b1+x0.y };
            float2 o1 = { fa[j][2]+b0+x1.x, fa[j][3]+b1+x1.y };
            *(float2*)&out[base0 + col] = o0;
            *(float2*)&out[base1 + col] = o1;
        }
    }
}

extern "C" void kernel_launch(void* const* d_in, const int* in_sizes, int n_in,
                              void* d_out, int out_size) {
    const float* x    = (const float*)d_in[0];
    const float* W_dw = (const float*)d_in[1];
    const float* b_dw = (const float*)d_in[2];
    const float* Wq   = (const float*)d_in[3];
    const float* bq   = (const float*)d_in[4];
    const float* Wk   = (const float*)d_in[5];
    const float* bk   = (const float*)d_in[6];
    const float* Wv   = (const float*)d_in[7];
    const float* bv   = (const float*)d_in[8];
    const float* Wo   = (const float*)d_in[9];
    const float* bo   = (const float*)d_in[10];
    const float* Bb   = (const float*)d_in[11];
    float* out = (float*)d_out;

    const int smem_k2 = (256*68 + 64*68*2 + 1024 + 4*4096)*4;
    const int smem_k3 = 198144;
    cudaFuncSetAttribute(kv_kernel,   cudaFuncAttributeMaxDynamicSharedMemorySize, smem_k2);
    cudaFuncSetAttribute(attn_kernel, cudaFuncAttributeMaxDynamicSharedMemorySize, smem_k3);

    ln_partial_kernel<<<dim3(B_SZ, 8), 256>>>(x);
    ln_final_kernel<<<1, 32>>>();
    kv_kernel<<<B_SZ, 256, smem_k2>>>(x, W_dw, b_dw, Wk, bk, Wv, bv);
    attn_kernel<<<dim3(B_SZ, 32), 256, smem_k3>>>(x, Wq, bq, Wo, bo, Bb, out);
}

// round 10
// speedup vs baseline: 4.4632x; 1.4094x over previous
#include <cuda_runtime.h>
#include <cuda_bf16.h>
#include <cstdint>
#include <math.h>

#define B_SZ 32
#define NQ   4096
#define MKV  256
#define DN   (64*NQ)

__device__ float g_stats[2*B_SZ];
__device__ float g_part[B_SZ*8*2];
__device__ float g_K[B_SZ*2*MKV*32];   // [b][h][j][d]
__device__ float g_V[B_SZ*2*32*MKV];   // [b][h][d][j]

__device__ __forceinline__ uint32_t smem_u32(const void* p){
    uint32_t a;
    asm("{ .reg .u64 t; cvta.to.shared.u64 t, %1; cvt.u32.u64 %0, t; }" : "=r"(a) : "l"(p));
    return a;
}
__device__ __forceinline__ float ex2f_(float v){
    float r; asm("ex2.approx.ftz.f32 %0, %1;" : "=f"(r) : "f"(v)); return r;
}
__device__ __forceinline__ void ldsm4(uint32_t addr, uint32_t r[4]){
    asm volatile("ldmatrix.sync.aligned.m8n8.x4.shared.b16 {%0,%1,%2,%3}, [%4];"
        : "=r"(r[0]),"=r"(r[1]),"=r"(r[2]),"=r"(r[3]) : "r"(addr));
}
__device__ __forceinline__ void ldsm2(uint32_t addr, uint32_t r[2]){
    asm volatile("ldmatrix.sync.aligned.m8n8.x2.shared.b16 {%0,%1}, [%2];"
        : "=r"(r[0]),"=r"(r[1]) : "r"(addr));
}
__device__ __forceinline__ void mma_bf16(float c[4], const uint32_t a[4], const uint32_t b[2]){
    asm volatile("mma.sync.aligned.m16n8k16.row.col.f32.bf16.bf16.f32 "
        "{%0,%1,%2,%3}, {%4,%5,%6,%7}, {%8,%9}, {%0,%1,%2,%3};"
        : "+f"(c[0]),"+f"(c[1]),"+f"(c[2]),"+f"(c[3])
        : "r"(a[0]),"r"(a[1]),"r"(a[2]),"r"(a[3]), "r"(b[0]),"r"(b[1]));
}
__device__ __forceinline__ uint32_t packbf(float a, float b){
    __nv_bfloat162 h = __floats2bfloat162_rn(a, b);
    return *(uint32_t*)&h;
}

// ---------- kernel 1: LN stats ----------
__global__ void ln_partial_kernel(const float* __restrict__ x){
    int b = blockIdx.x, p = blockIdx.y;
    const float4* xb = (const float4*)(x + (size_t)b*DN + (size_t)p*(DN/8));
    float s1=0.f, s2=0.f;
    for (int i = threadIdx.x; i < DN/32; i += blockDim.x){
        float4 v = xb[i];
        s1 += v.x+v.y+v.z+v.w; s2 += v.x*v.x+v.y*v.y+v.z*v.z+v.w*v.w;
    }
    #pragma unroll
    for (int o=16;o>0;o>>=1){ s1+=__shfl_xor_sync(~0u,s1,o); s2+=__shfl_xor_sync(~0u,s2,o); }
    __shared__ float r1[8], r2[8];
    int wid = threadIdx.x>>5, lid = threadIdx.x&31;
    if (lid==0){ r1[wid]=s1; r2[wid]=s2; }
    __syncthreads();
    if (threadIdx.x==0){
        float t1=0.f,t2=0.f;
        for (int i=0;i<(int)(blockDim.x>>5);i++){ t1+=r1[i]; t2+=r2[i]; }
        g_part[(b*8+p)*2]=t1; g_part[(b*8+p)*2+1]=t2;
    }
}
__global__ void ln_final_kernel(){
    int b = threadIdx.x;
    if (b < B_SZ){
        float t1=0.f,t2=0.f;
        for (int p=0;p<8;p++){ t1+=g_part[(b*8+p)*2]; t2+=g_part[(b*8+p)*2+1]; }
        float inv = 1.f/(float)DN, mu = t1*inv, var = t2*inv - mu*mu;
        g_stats[2*b]=mu; g_stats[2*b+1]=rsqrtf(var+1e-5f);
    }
}

// ---------- kernel 2: dw-conv + K/V proj (grid 32 x 2, 128 kv rows per block) ----------
__global__ void __launch_bounds__(256) kv_kernel(
    const float* __restrict__ x, const float* __restrict__ W_dw, const float* __restrict__ b_dw,
    const float* __restrict__ Wk, const float* __restrict__ bk,
    const float* __restrict__ Wv, const float* __restrict__ bv)
{
    int b = blockIdx.x, q = blockIdx.y, t = threadIdx.x;
    extern __shared__ float sm[];
    float* kv   = sm;              // 128*68 = 8704
    float* Wks  = kv + 128*68;     // 4352
    float* Wvs  = Wks + 64*68;     // 4352
    float* Wdws = Wvs + 64*68;     // 1024
    float* xs   = Wdws + 1024;     // 8192

    for (int i=t;i<64*64;i+=256){ int e=i>>6,c=i&63; Wks[e*68+c]=Wk[i]; Wvs[e*68+c]=Wv[i]; }
    for (int i=t;i<1024;i+=256) Wdws[i]=W_dw[i];
    const float* xb = x + (size_t)b*DN;

    int kyl = t>>4, kx = t&15;     // valid for t<128
    for (int cc=0;cc<64;cc+=4){
        __syncthreads();
        for (int i=t*4;i<8192;i+=1024){
            int cl=i>>11, z=i&2047;
            *(float4*)&xs[i] = *(const float4*)&xb[(cc+cl)*4096 + q*2048 + z];
        }
        __syncthreads();
        if (t < 128){
            #pragma unroll
            for (int cl=0;cl<4;cl++){
                float acc=b_dw[cc+cl];
                const float* xr=&xs[cl*2048 + kyl*256 + kx*4];
                const float* wr=&Wdws[(cc+cl)*16];
                #pragma unroll
                for (int sy=0;sy<4;sy++)
                    #pragma unroll
                    for (int sx=0;sx<4;sx++) acc += xr[sy*64+sx]*wr[sy*4+sx];
                kv[t*68+cc+cl]=acc;
            }
        }
    }
    __syncthreads();

    int mg=t&31, e0=(t>>5)*8;
    float acc[4][8];
    #pragma unroll
    for (int ee=0;ee<8;ee++){ float bb=bk[e0+ee]; for (int mm=0;mm<4;mm++) acc[mm][ee]=bb; }
    for (int c=0;c<64;c+=4){
        float4 kvv[4], wv[8];
        #pragma unroll
        for (int mm=0;mm<4;mm++) kvv[mm]=*(float4*)&kv[(mg+32*mm)*68+c];
        #pragma unroll
        for (int ee=0;ee<8;ee++) wv[ee]=*(float4*)&Wks[(e0+ee)*68+c];
        #pragma unroll
        for (int mm=0;mm<4;mm++)
            #pragma unroll
            for (int ee=0;ee<8;ee++)
                acc[mm][ee]+=kvv[mm].x*wv[ee].x+kvv[mm].y*wv[ee].y+kvv[mm].z*wv[ee].z+kvv[mm].w*wv[ee].w;
    }
    #pragma unroll
    for (int ee=0;ee<8;ee++){
        int e=e0+ee, h=e>>5, d=e&31;
        #pragma unroll
        for (int mm=0;mm<4;mm++){
            int m = 128*q + mg + 32*mm;
            g_K[((size_t)(b*2+h))*8192 + m*32 + d]=acc[mm][ee];
        }
    }
    #pragma unroll
    for (int ee=0;ee<8;ee++){ float bb=bv[e0+ee]; for (int mm=0;mm<4;mm++) acc[mm][ee]=bb; }
    for (int c=0;c<64;c+=4){
        float4 kvv[4], wv[8];
        #pragma unroll
        for (int mm=0;mm<4;mm++) kvv[mm]=*(float4*)&kv[(mg+32*mm)*68+c];
        #pragma unroll
        for (int ee=0;ee<8;ee++) wv[ee]=*(float4*)&Wvs[(e0+ee)*68+c];
        #pragma unroll
        for (int mm=0;mm<4;mm++)
            #pragma unroll
            for (int ee=0;ee<8;ee++)
                acc[mm][ee]+=kvv[mm].x*wv[ee].x+kvv[mm].y*wv[ee].y+kvv[mm].z*wv[ee].z+kvv[mm].w*wv[ee].w;
    }
    #pragma unroll
    for (int ee=0;ee<8;ee++){
        int e=e0+ee, h=e>>5, d=e&31;
        #pragma unroll
        for (int mm=0;mm<4;mm++){
            int m = 128*q + mg + 32*mm;
            g_V[((size_t)(b*2+h))*8192 + d*256 + m]=acc[mm][ee];
        }
    }
}

// ---------- kernel 3: mma.sync bf16 attention, register-resident Q/P/O ----------
// smem: XN[128][72] @0 (18432B) | WQ[64][72] @18432 (9216) | WO[64][72] @27648 (9216)
//       K 2x[256][40] @36864 (40960) | V 2x[32][264] @77824 (33792)
//       bqs @111616 (256) | bos @111872 (256)  => 112128 B
#define XN_OFF 0
#define WQ_OFF 18432
#define WO_OFF 27648
#define K_OFF  36864
#define V_OFF  77824
__global__ void __launch_bounds__(256, 2) attn_kernel(
    const float* __restrict__ x,
    const float* __restrict__ Wq, const float* __restrict__ bq,
    const float* __restrict__ Wo, const float* __restrict__ bo,
    const float* __restrict__ Bbias, float* __restrict__ out)
{
    int b = blockIdx.x, n0 = blockIdx.y*128, t = threadIdx.x;
    int w = t>>5, ln = t&31;
    int r = ln>>2, cq = (ln&3)*2;
    int row0 = 16*w;

    extern __shared__ char smraw[];
    uint32_t sb = smem_u32(smraw);
    __nv_bfloat16* XN  = (__nv_bfloat16*)(smraw + XN_OFF);
    __nv_bfloat16* WQs = (__nv_bfloat16*)(smraw + WQ_OFF);
    __nv_bfloat16* WOs = (__nv_bfloat16*)(smraw + WO_OFF);
    __nv_bfloat16* Ks  = (__nv_bfloat16*)(smraw + K_OFF);
    __nv_bfloat16* Vs  = (__nv_bfloat16*)(smraw + V_OFF);
    float* bqs = (float*)(smraw + 111616);
    float* bos = (float*)(smraw + 111872);

    float mu = g_stats[2*b], rstd = g_stats[2*b+1];
    const float* xb = x + (size_t)b*DN;

    // ---- staging ----
    for (int i=t;i<8192;i+=256){
        int c=i>>7, nl=i&127;
        XN[nl*72+c] = __float2bfloat16((xb[(size_t)c*4096 + n0 + nl]-mu)*rstd);
    }
    for (int i=t;i<4096;i+=256){
        int e=i>>6, c=i&63;
        WQs[e*72+c] = __float2bfloat16(Wq[i]);
        WOs[e*72+c] = __float2bfloat16(Wo[i]);   // [cout][e] row-major as-is
    }
    for (int i=t;i<16384;i+=256){
        int hh=i>>13, rr=i&8191;
        int j=rr>>5, d=rr&31;
        Ks[hh*10240 + j*40 + d] = __float2bfloat16(g_K[(size_t)(b*2+hh)*8192 + rr]);
    }
    for (int i=t;i<16384;i+=256){
        int hh=i>>13, rr=i&8191;
        int d=rr>>8, j=rr&255;
        Vs[hh*8448 + d*264 + j] = __float2bfloat16(g_V[(size_t)(b*2+hh)*8192 + rr]);
    }
    if (t<64){ bqs[t]=bq[t]; bos[t]=bo[t]; }
    __syncthreads();

    uint32_t u_xn = sb + XN_OFF, u_wq = sb + WQ_OFF, u_wo = sb + WO_OFF;
    uint32_t u_k = sb + K_OFF, u_v = sb + V_OFF;
    int a_row = row0 + (ln&15);
    int a_cb  = ((ln>>4)&1)*16;
    int b_row = ln&7;
    int b_cb  = ((ln>>3)&1)*16;

    // ---- Q projection: Q = XN @ Wq^T + bq, kept as A-fragments ----
    uint32_t qfrag[4][4];
    {
        float qa[8][4];
        #pragma unroll
        for (int j=0;j<8;j++){ qa[j][0]=0;qa[j][1]=0;qa[j][2]=0;qa[j][3]=0; }
        #pragma unroll
        for (int kt=0;kt<4;kt++){
            uint32_t a4[4];
            ldsm4(u_xn + a_row*144 + a_cb + kt*32, a4);
            #pragma unroll
            for (int j=0;j<8;j++){
                uint32_t b2[2];
                ldsm2(u_wq + (8*j+b_row)*144 + b_cb + kt*32, b2);
                mma_bf16(qa[j], a4, b2);
            }
        }
        #pragma unroll
        for (int u=0;u<4;u++){
            float b00=bqs[16*u+cq],   b01=bqs[16*u+cq+1];
            float b10=bqs[16*u+8+cq], b11=bqs[16*u+8+cq+1];
            qfrag[u][0] = packbf(qa[2*u][0]+b00,   qa[2*u][1]+b01);
            qfrag[u][1] = packbf(qa[2*u][2]+b00,   qa[2*u][3]+b01);
            qfrag[u][2] = packbf(qa[2*u+1][0]+b10, qa[2*u+1][1]+b11);
            qfrag[u][3] = packbf(qa[2*u+1][2]+b10, qa[2*u+1][3]+b11);
        }
    }

    const float C1 = 0.17677669529663687f*1.4426950408889634f;
    const float C2 = 1.4426950408889634f;

    // ---- per head: QK -> softmax -> AV, all A-operands in registers ----
    uint32_t ofrag[2][2][4];
    #pragma unroll
    for (int h=0; h<2; h++){
        float oacc[4][4];
        #pragma unroll
        for (int j=0;j<4;j++){ oacc[j][0]=0;oacc[j][1]=0;oacc[j][2]=0;oacc[j][3]=0; }
        float psum0 = 0.f, psum1 = 0.f;
        uint32_t kbase = u_k + h*20480;
        uint32_t vbase = u_v + h*16896;

        #pragma unroll 1
        for (int ch=0; ch<4; ch++){         // 64 j-cols per chunk
            float sa[8][4];
            #pragma unroll
            for (int j=0;j<8;j++){ sa[j][0]=0;sa[j][1]=0;sa[j][2]=0;sa[j][3]=0; }
            #pragma unroll
            for (int kt=0;kt<2;kt++){
                #pragma unroll
                for (int j=0;j<8;j++){
                    uint32_t b2[2];
                    ldsm2(kbase + (ch*64 + 8*j + b_row)*80 + b_cb + kt*32, b2);
                    mma_bf16(sa[j], qfrag[2*h+kt], b2);
                }
            }
            const float* Bg = Bbias + (size_t)(h*NQ + n0 + row0 + r)*MKV + ch*64 + cq;
            uint32_t pfrag[4][4];
            #pragma unroll
            for (int j=0;j<8;j++){
                float2 bA = *(const float2*)&Bg[8*j];
                float2 bB = *(const float2*)&Bg[8*j + 8*MKV];
                float p0 = ex2f_(fmaf(sa[j][0], C1, bA.x*C2));
                float p1 = ex2f_(fmaf(sa[j][1], C1, bA.y*C2));
                float p2 = ex2f_(fmaf(sa[j][2], C1, bB.x*C2));
                float p3 = ex2f_(fmaf(sa[j][3], C1, bB.y*C2));
                psum0 += p0+p1; psum1 += p2+p3;
                pfrag[j>>1][(j&1)*2+0] = packbf(p0, p1);
                pfrag[j>>1][(j&1)*2+1] = packbf(p2, p3);
            }
            #pragma unroll
            for (int u=0;u<4;u++){
                #pragma unroll
                for (int dt=0;dt<4;dt++){
                    uint32_t b2[2];
                    ldsm2(vbase + (8*dt + b_row)*528 + b_cb + ch*128 + u*32, b2);
                    mma_bf16(oacc[dt], pfrag[u], b2);
                }
            }
        }
        psum0 += __shfl_xor_sync(~0u, psum0, 1);
        psum0 += __shfl_xor_sync(~0u, psum0, 2);
        psum1 += __shfl_xor_sync(~0u, psum1, 1);
        psum1 += __shfl_xor_sync(~0u, psum1, 2);
        float inv0 = __fdividef(1.f, psum0), inv1 = __fdividef(1.f, psum1);
        #pragma unroll
        for (int u=0;u<2;u++){
            ofrag[h][u][0] = packbf(oacc[2*u][0]*inv0,   oacc[2*u][1]*inv0);
            ofrag[h][u][1] = packbf(oacc[2*u][2]*inv1,   oacc[2*u][3]*inv1);
            ofrag[h][u][2] = packbf(oacc[2*u+1][0]*inv0, oacc[2*u+1][1]*inv0);
            ofrag[h][u][3] = packbf(oacc[2*u+1][2]*inv1, oacc[2*u+1][3]*inv1);
        }
    }

    // ---- out projection (A = O fragments) + epilogue ----
    {
        float fa[8][4];
        #pragma unroll
        for (int j=0;j<8;j++){ fa[j][0]=0;fa[j][1]=0;fa[j][2]=0;fa[j][3]=0; }
        #pragma unroll
        for (int h=0;h<2;h++){
            #pragma unroll
            for (int u=0;u<2;u++){
                int kt = 2*h + u;
                #pragma unroll
                for (int j=0;j<8;j++){
                    uint32_t b2[2];
                    ldsm2(u_wo + (8*j+b_row)*144 + b_cb + kt*32, b2);
                    mma_bf16(fa[j], ofrag[h][u], b2);
                }
            }
        }
        size_t base0 = (size_t)b*DN + (size_t)(n0+row0+r)*64;
        size_t base1 = base0 + 8*64;
        #pragma unroll
        for (int j=0;j<8;j++){
            int col = 8*j + cq;
            float b0 = bos[col], b1 = bos[col+1];
            float2 x0 = *(const float2*)&x[base0 + col];
            float2 x1 = *(const float2*)&x[base1 + col];
            float2 o0 = { fa[j][0]+b0+x0.x, fa[j][1]+b1+x0.y };
            float2 o1 = { fa[j][2]+b0+x1.x, fa[j][3]+b1+x1.y };
            *(float2*)&out[base0 + col] = o0;
            *(float2*)&out[base1 + col] = o1;
        }
    }
}

extern "C" void kernel_launch(void* const* d_in, const int* in_sizes, int n_in,
                              void* d_out, int out_size) {
    const float* x    = (const float*)d_in[0];
    const float* W_dw = (const float*)d_in[1];
    const float* b_dw = (const float*)d_in[2];
    const float* Wq   = (const float*)d_in[3];
    const float* bq   = (const float*)d_in[4];
    const float* Wk   = (const float*)d_in[5];
    const float* bk   = (const float*)d_in[6];
    const float* Wv   = (const float*)d_in[7];
    const float* bv   = (const float*)d_in[8];
    const float* Wo   = (const float*)d_in[9];
    const float* bo   = (const float*)d_in[10];
    const float* Bb   = (const float*)d_in[11];
    float* out = (float*)d_out;

    const int smem_k2 = (128*68 + 64*68*2 + 1024 + 8192)*4;   // 106496 B
    const int smem_k3 = 112128;
    cudaFuncSetAttribute(kv_kernel,   cudaFuncAttributeMaxDynamicSharedMemorySize, smem_k2);
    cudaFuncSetAttribute(attn_kernel, cudaFuncAttributeMaxDynamicSharedMemorySize, smem_k3);

    ln_partial_kernel<<<dim3(B_SZ, 8), 256>>>(x);
    ln_final_kernel<<<1, 32>>>();
    kv_kernel<<<dim3(B_SZ, 2), 256, smem_k2>>>(x, W_dw, b_dw, Wk, bk, Wv, bv);
    attn_kernel<<<dim3(B_SZ, 32), 256, smem_k3>>>(x, Wq, bq, Wo, bo, Bb, out);
}

// round 14
// speedup vs baseline: 4.5080x; 1.0100x over previous
#include <cuda_runtime.h>
#include <cuda_bf16.h>
#include <cstdint>
#include <math.h>

#define B_SZ 32
#define NQ   4096
#define MKV  256
#define DN   (64*NQ)

__device__ float g_part[B_SZ*2*2];     // per (batch, half): s1, s2
__device__ float g_K[B_SZ*2*MKV*32];   // [b][h][j][d]
__device__ float g_V[B_SZ*2*32*MKV];   // [b][h][d][j]

__device__ __forceinline__ uint32_t smem_u32(const void* p){
    uint32_t a;
    asm("{ .reg .u64 t; cvta.to.shared.u64 t, %1; cvt.u32.u64 %0, t; }" : "=r"(a) : "l"(p));
    return a;
}
__device__ __forceinline__ float ex2f_(float v){
    float r; asm("ex2.approx.ftz.f32 %0, %1;" : "=f"(r) : "f"(v)); return r;
}
__device__ __forceinline__ void ldsm4(uint32_t addr, uint32_t r[4]){
    asm volatile("ldmatrix.sync.aligned.m8n8.x4.shared.b16 {%0,%1,%2,%3}, [%4];"
        : "=r"(r[0]),"=r"(r[1]),"=r"(r[2]),"=r"(r[3]) : "r"(addr));
}
__device__ __forceinline__ void mma_bf16(float c[4], const uint32_t a[4], const uint32_t b[2]){
    asm volatile("mma.sync.aligned.m16n8k16.row.col.f32.bf16.bf16.f32 "
        "{%0,%1,%2,%3}, {%4,%5,%6,%7}, {%8,%9}, {%0,%1,%2,%3};"
        : "+f"(c[0]),"+f"(c[1]),"+f"(c[2]),"+f"(c[3])
        : "r"(a[0]),"r"(a[1]),"r"(a[2]),"r"(a[3]), "r"(b[0]),"r"(b[1]));
}
__device__ __forceinline__ uint32_t packbf(float a, float b){
    __nv_bfloat162 h = __floats2bfloat162_rn(a, b);
    return *(uint32_t*)&h;
}

// ---------- kernel 1: dw-conv + K/V proj + LN partial stats ----------
// grid (32 batches, 2 halves), 256 thr
__global__ void __launch_bounds__(256) kv_kernel(
    const float* __restrict__ x, const float* __restrict__ W_dw, const float* __restrict__ b_dw,
    const float* __restrict__ Wk, const float* __restrict__ bk,
    const float* __restrict__ Wv, const float* __restrict__ bv)
{
    int b = blockIdx.x, q = blockIdx.y, t = threadIdx.x;
    extern __shared__ float sm[];
    float* kv   = sm;              // 128*68
    float* Wks  = kv + 128*68;
    float* Wvs  = Wks + 64*68;
    float* Wdws = Wvs + 64*68;
    float* xs   = Wdws + 1024;     // 8192
    __shared__ float red1[8], red2[8];

    for (int i=t;i<64*64;i+=256){ int e=i>>6,c=i&63; Wks[e*68+c]=Wk[i]; Wvs[e*68+c]=Wv[i]; }
    for (int i=t;i<1024;i+=256) Wdws[i]=W_dw[i];
    const float* xb = x + (size_t)b*DN;

    float s1 = 0.f, s2 = 0.f;
    int kyl = t>>4, kx = t&15;
    for (int cc=0;cc<64;cc+=4){
        __syncthreads();
        for (int i=t*4;i<8192;i+=1024){
            int cl=i>>11, z=i&2047;
            float4 v = *(const float4*)&xb[(cc+cl)*4096 + q*2048 + z];
            *(float4*)&xs[i] = v;
            s1 += v.x+v.y+v.z+v.w;
            s2 += v.x*v.x+v.y*v.y+v.z*v.z+v.w*v.w;
        }
        __syncthreads();
        if (t < 128){
            #pragma unroll
            for (int cl=0;cl<4;cl++){
                float acc=b_dw[cc+cl];
                const float* xr=&xs[cl*2048 + kyl*256 + kx*4];
                const float* wr=&Wdws[(cc+cl)*16];
                #pragma unroll
                for (int sy=0;sy<4;sy++)
                    #pragma unroll
                    for (int sx=0;sx<4;sx++) acc += xr[sy*64+sx]*wr[sy*4+sx];
                kv[t*68+cc+cl]=acc;
            }
        }
    }
    // LN partial reduce
    #pragma unroll
    for (int o=16;o>0;o>>=1){ s1+=__shfl_xor_sync(~0u,s1,o); s2+=__shfl_xor_sync(~0u,s2,o); }
    if ((t&31)==0){ red1[t>>5]=s1; red2[t>>5]=s2; }
    __syncthreads();
    if (t==0){
        float a=0.f,c=0.f;
        #pragma unroll
        for (int i=0;i<8;i++){ a+=red1[i]; c+=red2[i]; }
        g_part[(b*2+q)*2]=a; g_part[(b*2+q)*2+1]=c;
    }

    int mg=t&31, e0=(t>>5)*8;
    float acc[4][8];
    #pragma unroll
    for (int ee=0;ee<8;ee++){ float bb=bk[e0+ee]; for (int mm=0;mm<4;mm++) acc[mm][ee]=bb; }
    for (int c=0;c<64;c+=4){
        float4 kvv[4], wv[8];
        #pragma unroll
        for (int mm=0;mm<4;mm++) kvv[mm]=*(float4*)&kv[(mg+32*mm)*68+c];
        #pragma unroll
        for (int ee=0;ee<8;ee++) wv[ee]=*(float4*)&Wks[(e0+ee)*68+c];
        #pragma unroll
        for (int mm=0;mm<4;mm++)
            #pragma unroll
            for (int ee=0;ee<8;ee++)
                acc[mm][ee]+=kvv[mm].x*wv[ee].x+kvv[mm].y*wv[ee].y+kvv[mm].z*wv[ee].z+kvv[mm].w*wv[ee].w;
    }
    #pragma unroll
    for (int ee=0;ee<8;ee++){
        int e=e0+ee, h=e>>5, d=e&31;
        #pragma unroll
        for (int mm=0;mm<4;mm++){
            int m = 128*q + mg + 32*mm;
            g_K[((size_t)(b*2+h))*8192 + m*32 + d]=acc[mm][ee];
        }
    }
    #pragma unroll
    for (int ee=0;ee<8;ee++){ float bb=bv[e0+ee]; for (int mm=0;mm<4;mm++) acc[mm][ee]=bb; }
    for (int c=0;c<64;c+=4){
        float4 kvv[4], wv[8];
        #pragma unroll
        for (int mm=0;mm<4;mm++) kvv[mm]=*(float4*)&kv[(mg+32*mm)*68+c];
        #pragma unroll
        for (int ee=0;ee<8;ee++) wv[ee]=*(float4*)&Wvs[(e0+ee)*68+c];
        #pragma unroll
        for (int mm=0;mm<4;mm++)
            #pragma unroll
            for (int ee=0;ee<8;ee++)
                acc[mm][ee]+=kvv[mm].x*wv[ee].x+kvv[mm].y*wv[ee].y+kvv[mm].z*wv[ee].z+kvv[mm].w*wv[ee].w;
    }
    #pragma unroll
    for (int ee=0;ee<8;ee++){
        int e=e0+ee, h=e>>5, d=e&31;
        #pragma unroll
        for (int mm=0;mm<4;mm++){
            int m = 128*q + mg + 32*mm;
            g_V[((size_t)(b*2+h))*8192 + d*256 + m]=acc[mm][ee];
        }
    }
}

// ---------- kernel 2: mma.sync bf16 attention, register-resident Q/P/O ----------
#define XN_OFF 0
#define WQ_OFF 18432
#define WO_OFF 27648
#define K_OFF  36864
#define V_OFF  77824
__global__ void __launch_bounds__(256, 2) attn_kernel(
    const float* __restrict__ x,
    const float* __restrict__ Wq, const float* __restrict__ bq,
    const float* __restrict__ Wo, const float* __restrict__ bo,
    const float* __restrict__ Bbias, float* __restrict__ out)
{
    int b = blockIdx.x, n0 = blockIdx.y*128, t = threadIdx.x;
    int w = t>>5, ln = t&31;
    int r = ln>>2, cq = (ln&3)*2;
    int row0 = 16*w;

    extern __shared__ char smraw[];
    uint32_t sb = smem_u32(smraw);
    __nv_bfloat16* XN  = (__nv_bfloat16*)(smraw + XN_OFF);
    __nv_bfloat16* WQs = (__nv_bfloat16*)(smraw + WQ_OFF);
    __nv_bfloat16* WOs = (__nv_bfloat16*)(smraw + WO_OFF);
    __nv_bfloat16* Ks  = (__nv_bfloat16*)(smraw + K_OFF);
    __nv_bfloat16* Vs  = (__nv_bfloat16*)(smraw + V_OFF);
    float* bqs = (float*)(smraw + 111616);
    float* bos = (float*)(smraw + 111872);

    float p0s = g_part[b*4+0], p0q = g_part[b*4+1];
    float p1s = g_part[b*4+2], p1q = g_part[b*4+3];
    float invn = 1.f/(float)DN;
    float mu = (p0s+p1s)*invn;
    float rstd = rsqrtf((p0q+p1q)*invn - mu*mu + 1e-5f);
    const float* xb = x + (size_t)b*DN;

    // ---- staging ----
    for (int i=t;i<8192;i+=256){
        int c=i>>7, nl=i&127;
        XN[nl*72+c] = __float2bfloat16((xb[(size_t)c*4096 + n0 + nl]-mu)*rstd);
    }
    for (int i=t;i<4096;i+=256){
        int e=i>>6, c=i&63;
        WQs[e*72+c] = __float2bfloat16(Wq[i]);
        WOs[e*72+c] = __float2bfloat16(Wo[i]);
    }
    for (int i=t;i<16384;i+=256){
        int hh=i>>13, rr=i&8191;
        int j=rr>>5, d=rr&31;
        Ks[hh*10240 + j*40 + d] = __float2bfloat16(g_K[(size_t)(b*2+hh)*8192 + rr]);
    }
    for (int i=t;i<16384;i+=256){
        int hh=i>>13, rr=i&8191;
        int d=rr>>8, j=rr&255;
        Vs[hh*8448 + d*264 + j] = __float2bfloat16(g_V[(size_t)(b*2+hh)*8192 + rr]);
    }
    if (t<64){ bqs[t]=bq[t]; bos[t]=bo[t]; }
    __syncthreads();

    uint32_t u_xn = sb + XN_OFF, u_wq = sb + WQ_OFF, u_wo = sb + WO_OFF;
    uint32_t u_k = sb + K_OFF, u_v = sb + V_OFF;
    int a_row  = row0 + (ln&15);
    int a_cb   = ((ln>>4)&1)*16;
    int b4_row = (ln&7) + (((ln>>4)&1)<<3);   // x4 B-operand lane mapping
    int b4_cb  = ((ln>>3)&1)*16;

    // ---- Q projection: Q = XN @ Wq^T + bq, kept as A-fragments ----
    uint32_t qfrag[4][4];
    {
        float qa[8][4];
        #pragma unroll
        for (int j=0;j<8;j++){ qa[j][0]=0;qa[j][1]=0;qa[j][2]=0;qa[j][3]=0; }
        #pragma unroll
        for (int kt=0;kt<4;kt++){
            uint32_t a4[4];
            ldsm4(u_xn + a_row*144 + a_cb + kt*32, a4);
            #pragma unroll
            for (int jp=0;jp<4;jp++){
                uint32_t b4[4];
                ldsm4(u_wq + (16*jp + b4_row)*144 + b4_cb + kt*32, b4);
                mma_bf16(qa[2*jp],   a4, &b4[0]);
                mma_bf16(qa[2*jp+1], a4, &b4[2]);
            }
        }
        #pragma unroll
        for (int u=0;u<4;u++){
            float b00=bqs[16*u+cq],   b01=bqs[16*u+cq+1];
            float b10=bqs[16*u+8+cq], b11=bqs[16*u+8+cq+1];
            qfrag[u][0] = packbf(qa[2*u][0]+b00,   qa[2*u][1]+b01);
            qfrag[u][1] = packbf(qa[2*u][2]+b00,   qa[2*u][3]+b01);
            qfrag[u][2] = packbf(qa[2*u+1][0]+b10, qa[2*u+1][1]+b11);
            qfrag[u][3] = packbf(qa[2*u+1][2]+b10, qa[2*u+1][3]+b11);
        }
    }

    const float C1 = 0.17677669529663687f*1.4426950408889634f;
    const float C2 = 1.4426950408889634f;

    // ---- per head: QK -> softmax -> AV ----
    uint32_t ofrag[2][2][4];
    #pragma unroll
    for (int h=0; h<2; h++){
        float oacc[4][4];
        #pragma unroll
        for (int j=0;j<4;j++){ oacc[j][0]=0;oacc[j][1]=0;oacc[j][2]=0;oacc[j][3]=0; }
        float psum0 = 0.f, psum1 = 0.f;
        uint32_t kbase = u_k + h*20480;
        uint32_t vbase = u_v + h*16896;

        #pragma unroll 1
        for (int ch=0; ch<4; ch++){
            float sa[8][4];
            #pragma unroll
            for (int j=0;j<8;j++){ sa[j][0]=0;sa[j][1]=0;sa[j][2]=0;sa[j][3]=0; }
            #pragma unroll
            for (int kt=0;kt<2;kt++){
                #pragma unroll
                for (int jp=0;jp<4;jp++){
                    uint32_t b4[4];
                    ldsm4(kbase + (ch*64 + 16*jp + b4_row)*80 + b4_cb + kt*32, b4);
                    mma_bf16(sa[2*jp],   qfrag[2*h+kt], &b4[0]);
                    mma_bf16(sa[2*jp+1], qfrag[2*h+kt], &b4[2]);
                }
            }
            const float* Bg = Bbias + (size_t)(h*NQ + n0 + row0 + r)*MKV + ch*64 + cq;
            uint32_t pfrag[4][4];
            #pragma unroll
            for (int j=0;j<8;j++){
                float2 bA = *(const float2*)&Bg[8*j];
                float2 bB = *(const float2*)&Bg[8*j + 8*MKV];
                float p0 = ex2f_(fmaf(sa[j][0], C1, bA.x*C2));
                float p1 = ex2f_(fmaf(sa[j][1], C1, bA.y*C2));
                float p2 = ex2f_(fmaf(sa[j][2], C1, bB.x*C2));
                float p3 = ex2f_(fmaf(sa[j][3], C1, bB.y*C2));
                psum0 += p0+p1; psum1 += p2+p3;
                pfrag[j>>1][(j&1)*2+0] = packbf(p0, p1);
                pfrag[j>>1][(j&1)*2+1] = packbf(p2, p3);
            }
            #pragma unroll
            for (int u=0;u<4;u++){
                #pragma unroll
                for (int dtp=0;dtp<2;dtp++){
                    uint32_t b4[4];
                    ldsm4(vbase + (16*dtp + b4_row)*528 + b4_cb + ch*128 + u*32, b4);
                    mma_bf16(oacc[2*dtp],   pfrag[u], &b4[0]);
                    mma_bf16(oacc[2*dtp+1], pfrag[u], &b4[2]);
                }
            }
        }
        psum0 += __shfl_xor_sync(~0u, psum0, 1);
        psum0 += __shfl_xor_sync(~0u, psum0, 2);
        psum1 += __shfl_xor_sync(~0u, psum1, 1);
        psum1 += __shfl_xor_sync(~0u, psum1, 2);
        float inv0 = __fdividef(1.f, psum0), inv1 = __fdividef(1.f, psum1);
        #pragma unroll
        for (int u=0;u<2;u++){
            ofrag[h][u][0] = packbf(oacc[2*u][0]*inv0,   oacc[2*u][1]*inv0);
            ofrag[h][u][1] = packbf(oacc[2*u][2]*inv1,   oacc[2*u][3]*inv1);
            ofrag[h][u][2] = packbf(oacc[2*u+1][0]*inv0, oacc[2*u+1][1]*inv0);
            ofrag[h][u][3] = packbf(oacc[2*u+1][2]*inv1, oacc[2*u+1][3]*inv1);
        }
    }

    // ---- out projection + epilogue ----
    {
        float fa[8][4];
        #pragma unroll
        for (int j=0;j<8;j++){ fa[j][0]=0;fa[j][1]=0;fa[j][2]=0;fa[j][3]=0; }
        #pragma unroll
        for (int h=0;h<2;h++){
            #pragma unroll
            for (int u=0;u<2;u++){
                int kt = 2*h + u;
                #pragma unroll
                for (int jp=0;jp<4;jp++){
                    uint32_t b4[4];
                    ldsm4(u_wo + (16*jp + b4_row)*144 + b4_cb + kt*32, b4);
                    mma_bf16(fa[2*jp],   ofrag[h][u], &b4[0]);
                    mma_bf16(fa[2*jp+1], ofrag[h][u], &b4[2]);
                }
            }
        }
        size_t base0 = (size_t)b*DN + (size_t)(n0+row0+r)*64;
        size_t base1 = base0 + 8*64;
        #pragma unroll
        for (int j=0;j<8;j++){
            int col = 8*j + cq;
            float b0 = bos[col], b1 = bos[col+1];
            float2 x0 = *(const float2*)&x[base0 + col];
            float2 x1 = *(const float2*)&x[base1 + col];
            float2 o0 = { fa[j][0]+b0+x0.x, fa[j][1]+b1+x0.y };
            float2 o1 = { fa[j][2]+b0+x1.x, fa[j][3]+b1+x1.y };
            *(float2*)&out[base0 + col] = o0;
            *(float2*)&out[base1 + col] = o1;
        }
    }
}

extern "C" void kernel_launch(void* const* d_in, const int* in_sizes, int n_in,
                              void* d_out, int out_size) {
    const float* x    = (const float*)d_in[0];
    const float* W_dw = (const float*)d_in[1];
    const float* b_dw = (const float*)d_in[2];
    const float* Wq   = (const float*)d_in[3];
    const float* bq   = (const float*)d_in[4];
    const float* Wk   = (const float*)d_in[5];
    const float* bk   = (const float*)d_in[6];
    const float* Wv   = (const float*)d_in[7];
    const float* bv   = (const float*)d_in[8];
    const float* Wo   = (const float*)d_in[9];
    const float* bo   = (const float*)d_in[10];
    const float* Bb   = (const float*)d_in[11];
    float* out = (float*)d_out;

    const int smem_k2 = (128*68 + 64*68*2 + 1024 + 8192)*4;   // 106496 B
    const int smem_k3 = 112128;
    cudaFuncSetAttribute(kv_kernel,   cudaFuncAttributeMaxDynamicSharedMemorySize, smem_k2);
    cudaFuncSetAttribute(attn_kernel, cudaFuncAttributeMaxDynamicSharedMemorySize, smem_k3);

    kv_kernel<<<dim3(B_SZ, 2), 256, smem_k2>>>(x, W_dw, b_dw, Wk, bk, Wv, bv);
    attn_kernel<<<dim3(B_SZ, 32), 256, smem_k3>>>(x, Wq, bq, Wo, bo, Bb, out);
}

// round 15
// speedup vs baseline: 5.1689x; 1.1466x over previous
#include <cuda_runtime.h>
#include <cuda_bf16.h>
#include <cstdint>
#include <math.h>

#define B_SZ 32
#define NQ   4096
#define MKV  256
#define DN   (64*NQ)
#define NT   4          // query tiles per CTA

__device__ float g_part[B_SZ*2*2];     // per (batch, half): s1, s2
__device__ float g_K[B_SZ*2*MKV*32];   // [b][h][j][d]
__device__ float g_V[B_SZ*2*32*MKV];   // [b][h][d][j]

__device__ __forceinline__ uint32_t smem_u32(const void* p){
    uint32_t a;
    asm("{ .reg .u64 t; cvta.to.shared.u64 t, %1; cvt.u32.u64 %0, t; }" : "=r"(a) : "l"(p));
    return a;
}
__device__ __forceinline__ float ex2f_(float v){
    float r; asm("ex2.approx.ftz.f32 %0, %1;" : "=f"(r) : "f"(v)); return r;
}
__device__ __forceinline__ void ldsm4(uint32_t addr, uint32_t r[4]){
    asm volatile("ldmatrix.sync.aligned.m8n8.x4.shared.b16 {%0,%1,%2,%3}, [%4];"
        : "=r"(r[0]),"=r"(r[1]),"=r"(r[2]),"=r"(r[3]) : "r"(addr));
}
__device__ __forceinline__ void mma_bf16(float c[4], const uint32_t a[4], const uint32_t b[2]){
    asm volatile("mma.sync.aligned.m16n8k16.row.col.f32.bf16.bf16.f32 "
        "{%0,%1,%2,%3}, {%4,%5,%6,%7}, {%8,%9}, {%0,%1,%2,%3};"
        : "+f"(c[0]),"+f"(c[1]),"+f"(c[2]),"+f"(c[3])
        : "r"(a[0]),"r"(a[1]),"r"(a[2]),"r"(a[3]), "r"(b[0]),"r"(b[1]));
}
__device__ __forceinline__ uint32_t packbf(float a, float b){
    __nv_bfloat162 h = __floats2bfloat162_rn(a, b);
    return *(uint32_t*)&h;
}

// ---------- kernel 1: dw-conv + K/V proj + LN partial stats ----------
__global__ void __launch_bounds__(256) kv_kernel(
    const float* __restrict__ x, const float* __restrict__ W_dw, const float* __restrict__ b_dw,
    const float* __restrict__ Wk, const float* __restrict__ bk,
    const float* __restrict__ Wv, const float* __restrict__ bv)
{
    int b = blockIdx.x, q = blockIdx.y, t = threadIdx.x;
    extern __shared__ float sm[];
    float* kv   = sm;              // 128*68
    float* Wks  = kv + 128*68;
    float* Wvs  = Wks + 64*68;
    float* Wdws = Wvs + 64*68;
    float* xs   = Wdws + 1024;     // 8192
    __shared__ float red1[8], red2[8];

    for (int i=t;i<64*64;i+=256){ int e=i>>6,c=i&63; Wks[e*68+c]=Wk[i]; Wvs[e*68+c]=Wv[i]; }
    for (int i=t;i<1024;i+=256) Wdws[i]=W_dw[i];
    const float* xb = x + (size_t)b*DN;

    float s1 = 0.f, s2 = 0.f;
    int kyl = t>>4, kx = t&15;
    for (int cc=0;cc<64;cc+=4){
        __syncthreads();
        for (int i=t*4;i<8192;i+=1024){
            int cl=i>>11, z=i&2047;
            float4 v = *(const float4*)&xb[(cc+cl)*4096 + q*2048 + z];
            *(float4*)&xs[i] = v;
            s1 += v.x+v.y+v.z+v.w;
            s2 += v.x*v.x+v.y*v.y+v.z*v.z+v.w*v.w;
        }
        __syncthreads();
        if (t < 128){
            #pragma unroll
            for (int cl=0;cl<4;cl++){
                float acc=b_dw[cc+cl];
                const float* xr=&xs[cl*2048 + kyl*256 + kx*4];
                const float* wr=&Wdws[(cc+cl)*16];
                #pragma unroll
                for (int sy=0;sy<4;sy++)
                    #pragma unroll
                    for (int sx=0;sx<4;sx++) acc += xr[sy*64+sx]*wr[sy*4+sx];
                kv[t*68+cc+cl]=acc;
            }
        }
    }
    #pragma unroll
    for (int o=16;o>0;o>>=1){ s1+=__shfl_xor_sync(~0u,s1,o); s2+=__shfl_xor_sync(~0u,s2,o); }
    if ((t&31)==0){ red1[t>>5]=s1; red2[t>>5]=s2; }
    __syncthreads();
    if (t==0){
        float a=0.f,c=0.f;
        #pragma unroll
        for (int i=0;i<8;i++){ a+=red1[i]; c+=red2[i]; }
        g_part[(b*2+q)*2]=a; g_part[(b*2+q)*2+1]=c;
    }

    int mg=t&31, e0=(t>>5)*8;
    float acc[4][8];
    #pragma unroll
    for (int ee=0;ee<8;ee++){ float bb=bk[e0+ee]; for (int mm=0;mm<4;mm++) acc[mm][ee]=bb; }
    for (int c=0;c<64;c+=4){
        float4 kvv[4], wv[8];
        #pragma unroll
        for (int mm=0;mm<4;mm++) kvv[mm]=*(float4*)&kv[(mg+32*mm)*68+c];
        #pragma unroll
        for (int ee=0;ee<8;ee++) wv[ee]=*(float4*)&Wks[(e0+ee)*68+c];
        #pragma unroll
        for (int mm=0;mm<4;mm++)
            #pragma unroll
            for (int ee=0;ee<8;ee++)
                acc[mm][ee]+=kvv[mm].x*wv[ee].x+kvv[mm].y*wv[ee].y+kvv[mm].z*wv[ee].z+kvv[mm].w*wv[ee].w;
    }
    #pragma unroll
    for (int ee=0;ee<8;ee++){
        int e=e0+ee, h=e>>5, d=e&31;
        #pragma unroll
        for (int mm=0;mm<4;mm++){
            int m = 128*q + mg + 32*mm;
            g_K[((size_t)(b*2+h))*8192 + m*32 + d]=acc[mm][ee];
        }
    }
    #pragma unroll
    for (int ee=0;ee<8;ee++){ float bb=bv[e0+ee]; for (int mm=0;mm<4;mm++) acc[mm][ee]=bb; }
    for (int c=0;c<64;c+=4){
        float4 kvv[4], wv[8];
        #pragma unroll
        for (int mm=0;mm<4;mm++) kvv[mm]=*(float4*)&kv[(mg+32*mm)*68+c];
        #pragma unroll
        for (int ee=0;ee<8;ee++) wv[ee]=*(float4*)&Wvs[(e0+ee)*68+c];
        #pragma unroll
        for (int mm=0;mm<4;mm++)
            #pragma unroll
            for (int ee=0;ee<8;ee++)
                acc[mm][ee]+=kvv[mm].x*wv[ee].x+kvv[mm].y*wv[ee].y+kvv[mm].z*wv[ee].z+kvv[mm].w*wv[ee].w;
    }
    #pragma unroll
    for (int ee=0;ee<8;ee++){
        int e=e0+ee, h=e>>5, d=e&31;
        #pragma unroll
        for (int mm=0;mm<4;mm++){
            int m = 128*q + mg + 32*mm;
            g_V[((size_t)(b*2+h))*8192 + d*256 + m]=acc[mm][ee];
        }
    }
}

// ---------- kernel 2: persistent 4-tile mma.sync bf16 attention ----------
#define XN_OFF 0
#define WQ_OFF 18432
#define WO_OFF 27648
#define K_OFF  36864
#define V_OFF  77824
__global__ void __launch_bounds__(256, 2) attn_kernel(
    const float* __restrict__ x,
    const float* __restrict__ Wq, const float* __restrict__ bq,
    const float* __restrict__ Wo, const float* __restrict__ bo,
    const float* __restrict__ Bbias, float* __restrict__ out)
{
    int b = blockIdx.x, nbase = blockIdx.y*(128*NT), t = threadIdx.x;
    int w = t>>5, ln = t&31;
    int r = ln>>2, cq = (ln&3)*2;
    int row0 = 16*w;

    extern __shared__ char smraw[];
    uint32_t sb = smem_u32(smraw);
    __nv_bfloat16* XN  = (__nv_bfloat16*)(smraw + XN_OFF);
    __nv_bfloat16* WQs = (__nv_bfloat16*)(smraw + WQ_OFF);
    __nv_bfloat16* WOs = (__nv_bfloat16*)(smraw + WO_OFF);
    __nv_bfloat16* Ks  = (__nv_bfloat16*)(smraw + K_OFF);
    __nv_bfloat16* Vs  = (__nv_bfloat16*)(smraw + V_OFF);
    float* bqs = (float*)(smraw + 111616);
    float* bos = (float*)(smraw + 111872);

    float p0s = g_part[b*4+0], p0q = g_part[b*4+1];
    float p1s = g_part[b*4+2], p1q = g_part[b*4+3];
    float invn = 1.f/(float)DN;
    float mu = (p0s+p1s)*invn;
    float rstd = rsqrtf((p0q+p1q)*invn - mu*mu + 1e-5f);
    const float* xb = x + (size_t)b*DN;

    // ---- one-time staging: W, K, V, biases ----
    for (int i=t;i<4096;i+=256){
        int e=i>>6, c=i&63;
        WQs[e*72+c] = __float2bfloat16(Wq[i]);
        WOs[e*72+c] = __float2bfloat16(Wo[i]);
    }
    for (int i=t;i<16384;i+=256){
        int hh=i>>13, rr=i&8191;
        int j=rr>>5, d=rr&31;
        Ks[hh*10240 + j*40 + d] = __float2bfloat16(g_K[(size_t)(b*2+hh)*8192 + rr]);
    }
    for (int i=t;i<16384;i+=256){
        int hh=i>>13, rr=i&8191;
        int d=rr>>8, j=rr&255;
        Vs[hh*8448 + d*264 + j] = __float2bfloat16(g_V[(size_t)(b*2+hh)*8192 + rr]);
    }
    if (t<64){ bqs[t]=bq[t]; bos[t]=bo[t]; }

    uint32_t u_xn = sb + XN_OFF, u_wq = sb + WQ_OFF, u_wo = sb + WO_OFF;
    uint32_t u_k = sb + K_OFF, u_v = sb + V_OFF;
    int a_row  = row0 + (ln&15);
    int a_cb   = ((ln>>4)&1)*16;
    int b4_row = (ln&7) + (((ln>>4)&1)<<3);
    int b4_cb  = ((ln>>3)&1)*16;

    const float C1 = 0.17677669529663687f*1.4426950408889634f;
    const float C2 = 1.4426950408889634f;

    for (int it=0; it<NT; it++){
        int n0 = nbase + it*128;
        __syncthreads();                 // previous tile done with XN (and 1st iter: covers nothing stale)
        for (int i=t;i<8192;i+=256){
            int c=i>>7, nl=i&127;
            XN[nl*72+c] = __float2bfloat16((xb[(size_t)c*4096 + n0 + nl]-mu)*rstd);
        }
        __syncthreads();                 // XN (+ one-time staging on iter 0) visible

        // ---- Q projection ----
        uint32_t qfrag[4][4];
        {
            float qa[8][4];
            #pragma unroll
            for (int j=0;j<8;j++){ qa[j][0]=0;qa[j][1]=0;qa[j][2]=0;qa[j][3]=0; }
            #pragma unroll
            for (int kt=0;kt<4;kt++){
                uint32_t a4[4];
                ldsm4(u_xn + a_row*144 + a_cb + kt*32, a4);
                #pragma unroll
                for (int jp=0;jp<4;jp++){
                    uint32_t b4[4];
                    ldsm4(u_wq + (16*jp + b4_row)*144 + b4_cb + kt*32, b4);
                    mma_bf16(qa[2*jp],   a4, &b4[0]);
                    mma_bf16(qa[2*jp+1], a4, &b4[2]);
                }
            }
            #pragma unroll
            for (int u=0;u<4;u++){
                float b00=bqs[16*u+cq],   b01=bqs[16*u+cq+1];
                float b10=bqs[16*u+8+cq], b11=bqs[16*u+8+cq+1];
                qfrag[u][0] = packbf(qa[2*u][0]+b00,   qa[2*u][1]+b01);
                qfrag[u][1] = packbf(qa[2*u][2]+b00,   qa[2*u][3]+b01);
                qfrag[u][2] = packbf(qa[2*u+1][0]+b10, qa[2*u+1][1]+b11);
                qfrag[u][3] = packbf(qa[2*u+1][2]+b10, qa[2*u+1][3]+b11);
            }
        }

        // ---- per head: QK -> softmax -> AV ----
        uint32_t ofrag[2][2][4];
        #pragma unroll
        for (int h=0; h<2; h++){
            float oacc[4][4];
            #pragma unroll
            for (int j=0;j<4;j++){ oacc[j][0]=0;oacc[j][1]=0;oacc[j][2]=0;oacc[j][3]=0; }
            float psum0 = 0.f, psum1 = 0.f;
            uint32_t kbase = u_k + h*20480;
            uint32_t vbase = u_v + h*16896;

            #pragma unroll 1
            for (int ch=0; ch<4; ch++){
                float sa[8][4];
                #pragma unroll
                for (int j=0;j<8;j++){ sa[j][0]=0;sa[j][1]=0;sa[j][2]=0;sa[j][3]=0; }
                #pragma unroll
                for (int kt=0;kt<2;kt++){
                    #pragma unroll
                    for (int jp=0;jp<4;jp++){
                        uint32_t b4[4];
                        ldsm4(kbase + (ch*64 + 16*jp + b4_row)*80 + b4_cb + kt*32, b4);
                        mma_bf16(sa[2*jp],   qfrag[2*h+kt], &b4[0]);
                        mma_bf16(sa[2*jp+1], qfrag[2*h+kt], &b4[2]);
                    }
                }
                const float* Bg = Bbias + (size_t)(h*NQ + n0 + row0 + r)*MKV + ch*64 + cq;
                uint32_t pfrag[4][4];
                #pragma unroll
                for (int j=0;j<8;j++){
                    float2 bA = *(const float2*)&Bg[8*j];
                    float2 bB = *(const float2*)&Bg[8*j + 8*MKV];
                    float p0 = ex2f_(fmaf(sa[j][0], C1, bA.x*C2));
                    float p1 = ex2f_(fmaf(sa[j][1], C1, bA.y*C2));
                    float p2 = ex2f_(fmaf(sa[j][2], C1, bB.x*C2));
                    float p3 = ex2f_(fmaf(sa[j][3], C1, bB.y*C2));
                    psum0 += p0+p1; psum1 += p2+p3;
                    pfrag[j>>1][(j&1)*2+0] = packbf(p0, p1);
                    pfrag[j>>1][(j&1)*2+1] = packbf(p2, p3);
                }
                #pragma unroll
                for (int u=0;u<4;u++){
                    #pragma unroll
                    for (int dtp=0;dtp<2;dtp++){
                        uint32_t b4[4];
                        ldsm4(vbase + (16*dtp + b4_row)*528 + b4_cb + ch*128 + u*32, b4);
                        mma_bf16(oacc[2*dtp],   pfrag[u], &b4[0]);
                        mma_bf16(oacc[2*dtp+1], pfrag[u], &b4[2]);
                    }
                }
            }
            psum0 += __shfl_xor_sync(~0u, psum0, 1);
            psum0 += __shfl_xor_sync(~0u, psum0, 2);
            psum1 += __shfl_xor_sync(~0u, psum1, 1);
            psum1 += __shfl_xor_sync(~0u, psum1, 2);
            float inv0 = __fdividef(1.f, psum0), inv1 = __fdividef(1.f, psum1);
            #pragma unroll
            for (int u=0;u<2;u++){
                ofrag[h][u][0] = packbf(oacc[2*u][0]*inv0,   oacc[2*u][1]*inv0);
                ofrag[h][u][1] = packbf(oacc[2*u][2]*inv1,   oacc[2*u][3]*inv1);
                ofrag[h][u][2] = packbf(oacc[2*u+1][0]*inv0, oacc[2*u+1][1]*inv0);
                ofrag[h][u][3] = packbf(oacc[2*u+1][2]*inv1, oacc[2*u+1][3]*inv1);
            }
        }

        // ---- out projection + epilogue ----
        {
            float fa[8][4];
            #pragma unroll
            for (int j=0;j<8;j++){ fa[j][0]=0;fa[j][1]=0;fa[j][2]=0;fa[j][3]=0; }
            #pragma unroll
            for (int h=0;h<2;h++){
                #pragma unroll
                for (int u=0;u<2;u++){
                    int kt = 2*h + u;
                    #pragma unroll
                    for (int jp=0;jp<4;jp++){
                        uint32_t b4[4];
                        ldsm4(u_wo + (16*jp + b4_row)*144 + b4_cb + kt*32, b4);
                        mma_bf16(fa[2*jp],   ofrag[h][u], &b4[0]);
                        mma_bf16(fa[2*jp+1], ofrag[h][u], &b4[2]);
                    }
                }
            }
            size_t base0 = (size_t)b*DN + (size_t)(n0+row0+r)*64;
            size_t base1 = base0 + 8*64;
            #pragma unroll
            for (int j=0;j<8;j++){
                int col = 8*j + cq;
                float b0 = bos[col], b1 = bos[col+1];
                float2 x0 = *(const float2*)&x[base0 + col];
                float2 x1 = *(const float2*)&x[base1 + col];
                float2 o0 = { fa[j][0]+b0+x0.x, fa[j][1]+b1+x0.y };
                float2 o1 = { fa[j][2]+b0+x1.x, fa[j][3]+b1+x1.y };
                *(float2*)&out[base0 + col] = o0;
                *(float2*)&out[base1 + col] = o1;
            }
        }
    }
}

extern "C" void kernel_launch(void* const* d_in, const int* in_sizes, int n_in,
                              void* d_out, int out_size) {
    const float* x    = (const float*)d_in[0];
    const float* W_dw = (const float*)d_in[1];
    const float* b_dw = (const float*)d_in[2];
    const float* Wq   = (const float*)d_in[3];
    const float* bq   = (const float*)d_in[4];
    const float* Wk   = (const float*)d_in[5];
    const float* bk   = (const float*)d_in[6];
    const float* Wv   = (const float*)d_in[7];
    const float* bv   = (const float*)d_in[8];
    const float* Wo   = (const float*)d_in[9];
    const float* bo   = (const float*)d_in[10];
    const float* Bb   = (const float*)d_in[11];
    float* out = (float*)d_out;

    const int smem_k2 = (128*68 + 64*68*2 + 1024 + 8192)*4;   // 106496 B
    const int smem_k3 = 112128;
    cudaFuncSetAttribute(kv_kernel,   cudaFuncAttributeMaxDynamicSharedMemorySize, smem_k2);
    cudaFuncSetAttribute(attn_kernel, cudaFuncAttributeMaxDynamicSharedMemorySize, smem_k3);

    kv_kernel<<<dim3(B_SZ, 2), 256, smem_k2>>>(x, W_dw, b_dw, Wk, bk, Wv, bv);
    attn_kernel<<<dim3(B_SZ, 32/NT), 256, smem_k3>>>(x, Wq, bq, Wo, bo, Bb, out);
}

// round 17
// speedup vs baseline: 5.2662x; 1.0188x over previous
#include <cuda_runtime.h>
#include <cuda_bf16.h>
#include <cstdint>
#include <math.h>

#define B_SZ 32
#define NQ   4096
#define MKV  256
#define DN   (64*NQ)
#define NCTA 304

__device__ float g_part[B_SZ*2*2];
__device__ __align__(16) __nv_bfloat16 g_Kb[B_SZ*2*10240];  // [b][h][j*40+d]
__device__ __align__(16) __nv_bfloat16 g_Vb[B_SZ*2*8448];   // [b][h][d*264+j]
__device__ __align__(16) __nv_bfloat16 g_B2[2*NQ*MKV];      // bf16(B * log2e)

__device__ __forceinline__ uint32_t smem_u32(const void* p){
    uint32_t a;
    asm("{ .reg .u64 t; cvta.to.shared.u64 t, %1; cvt.u32.u64 %0, t; }" : "=r"(a) : "l"(p));
    return a;
}
__device__ __forceinline__ float ex2f_(float v){
    float r; asm("ex2.approx.ftz.f32 %0, %1;" : "=f"(r) : "f"(v)); return r;
}
__device__ __forceinline__ void ldsm4(uint32_t addr, uint32_t r[4]){
    asm volatile("ldmatrix.sync.aligned.m8n8.x4.shared.b16 {%0,%1,%2,%3}, [%4];"
        : "=r"(r[0]),"=r"(r[1]),"=r"(r[2]),"=r"(r[3]) : "r"(addr));
}
__device__ __forceinline__ void mma_bf16(float c[4], const uint32_t a[4], const uint32_t b[2]){
    asm volatile("mma.sync.aligned.m16n8k16.row.col.f32.bf16.bf16.f32 "
        "{%0,%1,%2,%3}, {%4,%5,%6,%7}, {%8,%9}, {%0,%1,%2,%3};"
        : "+f"(c[0]),"+f"(c[1]),"+f"(c[2]),"+f"(c[3])
        : "r"(a[0]),"r"(a[1]),"r"(a[2]),"r"(a[3]), "r"(b[0]),"r"(b[1]));
}
__device__ __forceinline__ uint32_t packbf(float a, float b){
    __nv_bfloat162 h = __floats2bfloat162_rn(a, b);
    return *(uint32_t*)&h;
}

// ---------- kernel 0: bias -> bf16 pre-scaled by log2e ----------
__global__ void bconv_kernel(const float* __restrict__ B){
    int i = blockIdx.x*1024 + threadIdx.x;
    g_B2[i] = __float2bfloat16(B[i]*1.4426950408889634f);
}

// ---------- kernel 1: dw-conv + K/V proj (bf16, smem-image layout) + LN stats ----------
__global__ void __launch_bounds__(256) kv_kernel(
    const float* __restrict__ x, const float* __restrict__ W_dw, const float* __restrict__ b_dw,
    const float* __restrict__ Wk, const float* __restrict__ bk,
    const float* __restrict__ Wv, const float* __restrict__ bv)
{
    int b = blockIdx.x, q = blockIdx.y, t = threadIdx.x;
    extern __shared__ float sm[];
    float* kv   = sm;              // 128*68
    float* Wks  = kv + 128*68;
    float* Wvs  = Wks + 64*68;
    float* Wdws = Wvs + 64*68;
    float* xs   = Wdws + 1024;     // 8192
    __shared__ float red1[8], red2[8];

    for (int i=t;i<64*64;i+=256){ int e=i>>6,c=i&63; Wks[e*68+c]=Wk[i]; Wvs[e*68+c]=Wv[i]; }
    for (int i=t;i<1024;i+=256) Wdws[i]=W_dw[i];
    const float* xb = x + (size_t)b*DN;

    float s1 = 0.f, s2 = 0.f;
    int kyl = t>>4, kx = t&15;
    for (int cc=0;cc<64;cc+=4){
        __syncthreads();
        for (int i=t*4;i<8192;i+=1024){
            int cl=i>>11, z=i&2047;
            float4 v = *(const float4*)&xb[(cc+cl)*4096 + q*2048 + z];
            *(float4*)&xs[i] = v;
            s1 += v.x+v.y+v.z+v.w;
            s2 += v.x*v.x+v.y*v.y+v.z*v.z+v.w*v.w;
        }
        __syncthreads();
        if (t < 128){
            #pragma unroll
            for (int cl=0;cl<4;cl++){
                float acc=b_dw[cc+cl];
                const float* xr=&xs[cl*2048 + kyl*256 + kx*4];
                const float* wr=&Wdws[(cc+cl)*16];
                #pragma unroll
                for (int sy=0;sy<4;sy++)
                    #pragma unroll
                    for (int sx=0;sx<4;sx++) acc += xr[sy*64+sx]*wr[sy*4+sx];
                kv[t*68+cc+cl]=acc;
            }
        }
    }
    #pragma unroll
    for (int o=16;o>0;o>>=1){ s1+=__shfl_xor_sync(~0u,s1,o); s2+=__shfl_xor_sync(~0u,s2,o); }
    if ((t&31)==0){ red1[t>>5]=s1; red2[t>>5]=s2; }
    __syncthreads();
    if (t==0){
        float a=0.f,c=0.f;
        #pragma unroll
        for (int i=0;i<8;i++){ a+=red1[i]; c+=red2[i]; }
        g_part[(b*2+q)*2]=a; g_part[(b*2+q)*2+1]=c;
    }

    int mg=t&31, e0=(t>>5)*8;
    float acc[4][8];
    #pragma unroll
    for (int ee=0;ee<8;ee++){ float bb=bk[e0+ee]; for (int mm=0;mm<4;mm++) acc[mm][ee]=bb; }
    for (int c=0;c<64;c+=4){
        float4 kvv[4], wv[8];
        #pragma unroll
        for (int mm=0;mm<4;mm++) kvv[mm]=*(float4*)&kv[(mg+32*mm)*68+c];
        #pragma unroll
        for (int ee=0;ee<8;ee++) wv[ee]=*(float4*)&Wks[(e0+ee)*68+c];
        #pragma unroll
        for (int mm=0;mm<4;mm++)
            #pragma unroll
            for (int ee=0;ee<8;ee++)
                acc[mm][ee]+=kvv[mm].x*wv[ee].x+kvv[mm].y*wv[ee].y+kvv[mm].z*wv[ee].z+kvv[mm].w*wv[ee].w;
    }
    #pragma unroll
    for (int ee=0;ee<8;ee++){
        int e=e0+ee, h=e>>5, d=e&31;
        #pragma unroll
        for (int mm=0;mm<4;mm++){
            int m = 128*q + mg + 32*mm;
            g_Kb[(size_t)(b*2+h)*10240 + m*40 + d] = __float2bfloat16(acc[mm][ee]);
        }
    }
    #pragma unroll
    for (int ee=0;ee<8;ee++){ float bb=bv[e0+ee]; for (int mm=0;mm<4;mm++) acc[mm][ee]=bb; }
    for (int c=0;c<64;c+=4){
        float4 kvv[4], wv[8];
        #pragma unroll
        for (int mm=0;mm<4;mm++) kvv[mm]=*(float4*)&kv[(mg+32*mm)*68+c];
        #pragma unroll
        for (int ee=0;ee<8;ee++) wv[ee]=*(float4*)&Wvs[(e0+ee)*68+c];
        #pragma unroll
        for (int mm=0;mm<4;mm++)
            #pragma unroll
            for (int ee=0;ee<8;ee++)
                acc[mm][ee]+=kvv[mm].x*wv[ee].x+kvv[mm].y*wv[ee].y+kvv[mm].z*wv[ee].z+kvv[mm].w*wv[ee].w;
    }
    #pragma unroll
    for (int ee=0;ee<8;ee++){
        int e=e0+ee, h=e>>5, d=e&31;
        #pragma unroll
        for (int mm=0;mm<4;mm++){
            int m = 128*q + mg + 32*mm;
            g_Vb[(size_t)(b*2+h)*8448 + d*264 + m] = __float2bfloat16(acc[mm][ee]);
        }
    }
}

// ---------- kernel 2: range-scheduled persistent mma.sync bf16 attention ----------
#define XN_OFF 0
#define WQ_OFF 18432
#define WO_OFF 27648
#define K_OFF  36864
#define V_OFF  77824
__global__ void __launch_bounds__(256, 2) attn_kernel(
    const float* __restrict__ x,
    const float* __restrict__ Wq, const float* __restrict__ bq,
    const float* __restrict__ Wo, const float* __restrict__ bo,
    float* __restrict__ out)
{
    int t = threadIdx.x;
    int w = t>>5, ln = t&31;
    int r = ln>>2, cq = (ln&3)*2;
    int row0 = 16*w;

    extern __shared__ char smraw[];
    uint32_t sb = smem_u32(smraw);
    __nv_bfloat16* XN  = (__nv_bfloat16*)(smraw + XN_OFF);
    __nv_bfloat16* WQs = (__nv_bfloat16*)(smraw + WQ_OFF);
    __nv_bfloat16* WOs = (__nv_bfloat16*)(smraw + WO_OFF);
    float* bqs = (float*)(smraw + 111616);
    float* bos = (float*)(smraw + 111872);

    // one-time W/bias staging
    for (int i=t;i<4096;i+=256){
        int e=i>>6, c=i&63;
        WQs[e*72+c] = __float2bfloat16(Wq[i]);
        WOs[e*72+c] = __float2bfloat16(Wo[i]);
    }
    if (t<64){ bqs[t]=bq[t]; bos[t]=bo[t]; }

    uint32_t u_xn = sb + XN_OFF, u_wq = sb + WQ_OFF, u_wo = sb + WO_OFF;
    uint32_t u_k = sb + K_OFF, u_v = sb + V_OFF;
    int a_row  = row0 + (ln&15);
    int a_cb   = ((ln>>4)&1)*16;
    int b4_row = (ln&7) + (((ln>>4)&1)<<3);
    int b4_cb  = ((ln>>3)&1)*16;

    const float C1 = 0.17677669529663687f*1.4426950408889634f;

    int u0 = (blockIdx.x * 1024) / NCTA;
    int u1 = ((blockIdx.x+1) * 1024) / NCTA;
    int bcur = -1;
    float mu = 0.f, rstd = 0.f;
    const float* xb = x;

    for (int u=u0; u<u1; u++){
        int b = u>>5, n0 = (u&31)*128;
        __syncthreads();                 // previous tile done with smem
        if (b != bcur){
            bcur = b;
            const uint4* ksrc = (const uint4*)(g_Kb + (size_t)b*20480);
            uint4* kdst = (uint4*)(smraw + K_OFF);
            for (int i=t;i<2560;i+=256) kdst[i] = ksrc[i];
            const uint4* vsrc = (const uint4*)(g_Vb + (size_t)b*16896);
            uint4* vdst = (uint4*)(smraw + V_OFF);
            for (int i=t;i<2112;i+=256) vdst[i] = vsrc[i];
            float invn = 1.f/(float)DN;
            mu = (g_part[b*4+0]+g_part[b*4+2])*invn;
            rstd = rsqrtf((g_part[b*4+1]+g_part[b*4+3])*invn - mu*mu + 1e-5f);
            xb = x + (size_t)b*DN;
        }
        for (int i=t;i<8192;i+=256){
            int c=i>>7, nl=i&127;
            XN[nl*72+c] = __float2bfloat16((xb[(size_t)c*4096 + n0 + nl]-mu)*rstd);
        }
        __syncthreads();

        // ---- Q projection ----
        uint32_t qfrag[4][4];
        {
            float qa[8][4];
            #pragma unroll
            for (int j=0;j<8;j++){ qa[j][0]=0;qa[j][1]=0;qa[j][2]=0;qa[j][3]=0; }
            #pragma unroll
            for (int kt=0;kt<4;kt++){
                uint32_t a4[4];
                ldsm4(u_xn + a_row*144 + a_cb + kt*32, a4);
                #pragma unroll
                for (int jp=0;jp<4;jp++){
                    uint32_t b4[4];
                    ldsm4(u_wq + (16*jp + b4_row)*144 + b4_cb + kt*32, b4);
                    mma_bf16(qa[2*jp],   a4, &b4[0]);
                    mma_bf16(qa[2*jp+1], a4, &b4[2]);
                }
            }
            #pragma unroll
            for (int uu=0;uu<4;uu++){
                float b00=bqs[16*uu+cq],   b01=bqs[16*uu+cq+1];
                float b10=bqs[16*uu+8+cq], b11=bqs[16*uu+8+cq+1];
                qfrag[uu][0] = packbf(qa[2*uu][0]+b00,   qa[2*uu][1]+b01);
                qfrag[uu][1] = packbf(qa[2*uu][2]+b00,   qa[2*uu][3]+b01);
                qfrag[uu][2] = packbf(qa[2*uu+1][0]+b10, qa[2*uu+1][1]+b11);
                qfrag[uu][3] = packbf(qa[2*uu+1][2]+b10, qa[2*uu+1][3]+b11);
            }
        }

        // ---- per head: QK -> softmax -> AV ----
        uint32_t ofrag[2][2][4];
        #pragma unroll
        for (int h=0; h<2; h++){
            float oacc[4][4];
            #pragma unroll
            for (int j=0;j<4;j++){ oacc[j][0]=0;oacc[j][1]=0;oacc[j][2]=0;oacc[j][3]=0; }
            float psum0 = 0.f, psum1 = 0.f;
            uint32_t kbase = u_k + h*20480;
            uint32_t vbase = u_v + h*16896;
            const uint32_t* Bgh = (const uint32_t*)g_B2
                + (((size_t)(h*NQ + n0 + row0 + r))*256 + cq)/2;

            #pragma unroll 1
            for (int ch=0; ch<4; ch++){
                // early bias loads (bf16x2, pre-scaled) — covered by QK MMA latency
                const uint32_t* Bg = Bgh + ch*32;
                uint32_t bu[16];
                #pragma unroll
                for (int j=0;j<8;j++){ bu[2*j] = Bg[4*j]; bu[2*j+1] = Bg[4*j + 1024]; }

                float sa[8][4];
                #pragma unroll
                for (int j=0;j<8;j++){ sa[j][0]=0;sa[j][1]=0;sa[j][2]=0;sa[j][3]=0; }
                #pragma unroll
                for (int kt=0;kt<2;kt++){
                    #pragma unroll
                    for (int jp=0;jp<4;jp++){
                        uint32_t b4[4];
                        ldsm4(kbase + (ch*64 + 16*jp + b4_row)*80 + b4_cb + kt*32, b4);
                        mma_bf16(sa[2*jp],   qfrag[2*h+kt], &b4[0]);
                        mma_bf16(sa[2*jp+1], qfrag[2*h+kt], &b4[2]);
                    }
                }
                uint32_t pfrag[4][4];
                #pragma unroll
                for (int j=0;j<8;j++){
                    float2 fA = __bfloat1622float2(*(__nv_bfloat162*)&bu[2*j]);
                    float2 fB = __bfloat1622float2(*(__nv_bfloat162*)&bu[2*j+1]);
                    float p0 = ex2f_(fmaf(sa[j][0], C1, fA.x));
                    float p1 = ex2f_(fmaf(sa[j][1], C1, fA.y));
                    float p2 = ex2f_(fmaf(sa[j][2], C1, fB.x));
                    float p3 = ex2f_(fmaf(sa[j][3], C1, fB.y));
                    psum0 += p0+p1; psum1 += p2+p3;
                    pfrag[j>>1][(j&1)*2+0] = packbf(p0, p1);
                    pfrag[j>>1][(j&1)*2+1] = packbf(p2, p3);
                }
                #pragma unroll
                for (int uu=0;uu<4;uu++){
                    #pragma unroll
                    for (int dtp=0;dtp<2;dtp++){
                        uint32_t b4[4];
                        ldsm4(vbase + (16*dtp + b4_row)*528 + b4_cb + ch*128 + uu*32, b4);
                        mma_bf16(oacc[2*dtp],   pfrag[uu], &b4[0]);
                        mma_bf16(oacc[2*dtp+1], pfrag[uu], &b4[2]);
                    }
                }
            }
            psum0 += __shfl_xor_sync(~0u, psum0, 1);
            psum0 += __shfl_xor_sync(~0u, psum0, 2);
            psum1 += __shfl_xor_sync(~0u, psum1, 1);
            psum1 += __shfl_xor_sync(~0u, psum1, 2);
            float inv0 = __fdividef(1.f, psum0), inv1 = __fdividef(1.f, psum1);
            #pragma unroll
            for (int uu=0;uu<2;uu++){
                ofrag[h][uu][0] = packbf(oacc[2*uu][0]*inv0,   oacc[2*uu][1]*inv0);
                ofrag[h][uu][1] = packbf(oacc[2*uu][2]*inv1,   oacc[2*uu][3]*inv1);
                ofrag[h][uu][2] = packbf(oacc[2*uu+1][0]*inv0, oacc[2*uu+1][1]*inv0);
                ofrag[h][uu][3] = packbf(oacc[2*uu+1][2]*inv1, oacc[2*uu+1][3]*inv1);
            }
        }

        // ---- out projection + epilogue ----
        {
            float fa[8][4];
            #pragma unroll
            for (int j=0;j<8;j++){ fa[j][0]=0;fa[j][1]=0;fa[j][2]=0;fa[j][3]=0; }
            #pragma unroll
            for (int h=0;h<2;h++){
                #pragma unroll
                for (int uu=0;uu<2;uu++){
                    int kt = 2*h + uu;
                    #pragma unroll
                    for (int jp=0;jp<4;jp++){
                        uint32_t b4[4];
                        ldsm4(u_wo + (16*jp + b4_row)*144 + b4_cb + kt*32, b4);
                        mma_bf16(fa[2*jp],   ofrag[h][uu], &b4[0]);
                        mma_bf16(fa[2*jp+1], ofrag[h][uu], &b4[2]);
                    }
                }
            }
            size_t base0 = (size_t)b*DN + (size_t)(n0+row0+r)*64;
            size_t base1 = base0 + 8*64;
            #pragma unroll
            for (int j=0;j<8;j++){
                int col = 8*j + cq;
                float b0 = bos[col], b1 = bos[col+1];
                float2 x0 = *(const float2*)&x[base0 + col];
                float2 x1 = *(const float2*)&x[base1 + col];
                float2 o0 = { fa[j][0]+b0+x0.x, fa[j][1]+b1+x0.y };
                float2 o1 = { fa[j][2]+b0+x1.x, fa[j][3]+b1+x1.y };
                *(float2*)&out[base0 + col] = o0;
                *(float2*)&out[base1 + col] = o1;
            }
        }
    }
}

extern "C" void kernel_launch(void* const* d_in, const int* in_sizes, int n_in,
                              void* d_out, int out_size) {
    const float* x    = (const float*)d_in[0];
    const float* W_dw = (const float*)d_in[1];
    const float* b_dw = (const float*)d_in[2];
    const float* Wq   = (const float*)d_in[3];
    const float* bq   = (const float*)d_in[4];
    const float* Wk   = (const float*)d_in[5];
    const float* bk   = (const float*)d_in[6];
    const float* Wv   = (const float*)d_in[7];
    const float* bv   = (const float*)d_in[8];
    const float* Wo   = (const float*)d_in[9];
    const float* bo   = (const float*)d_in[10];
    const float* Bb   = (const float*)d_in[11];
    float* out = (float*)d_out;

    const int smem_k2 = (128*68 + 64*68*2 + 1024 + 8192)*4;   // 106496 B
    const int smem_k3 = 112128;
    cudaFuncSetAttribute(kv_kernel,   cudaFuncAttributeMaxDynamicSharedMemorySize, smem_k2);
    cudaFuncSetAttribute(attn_kernel, cudaFuncAttributeMaxDynamicSharedMemorySize, smem_k3);

    bconv_kernel<<<2048, 1024>>>(Bb);
    kv_kernel<<<dim3(B_SZ, 2), 256, smem_k2>>>(x, W_dw, b_dw, Wk, bk, Wv, bv);
    attn_kernel<<<NCTA, 256, smem_k3>>>(x, Wq, bq, Wo, bo, out);
}